// round 5
// baseline (speedup 1.0000x reference)
#include <cuda_runtime.h>
#include <cuda_bf16.h>
#include <cstdint>

#define S_LEN   2048
#define BATCH   2
#define DIM     4096
#define NH      32
#define KVHEADS 8
#define HD      128
#define MROWS   (BATCH * S_LEN)     // 4096
#define KVDIM   (KVHEADS * HD)      // 1024
#define KDIM    4096

// ---------------- scratch (__device__ globals) ------------------------------
__device__ float g_q[(size_t)MROWS * DIM];
__device__ float g_k[(size_t)MROWS * KVDIM];
__device__ float g_v[(size_t)MROWS * KVDIM];

__device__ __nv_bfloat16 g_xhi[(size_t)MROWS * KDIM];
__device__ __nv_bfloat16 g_xlo[(size_t)MROWS * KDIM];
__device__ __nv_bfloat16 g_wqhi[(size_t)DIM * KDIM];
__device__ __nv_bfloat16 g_wqlo[(size_t)DIM * KDIM];
__device__ __nv_bfloat16 g_wkhi[(size_t)KVDIM * KDIM];
__device__ __nv_bfloat16 g_wklo[(size_t)KVDIM * KDIM];
__device__ __nv_bfloat16 g_wvhi[(size_t)KVDIM * KDIM];
__device__ __nv_bfloat16 g_wvlo[(size_t)KVDIM * KDIM];
__device__ __nv_bfloat16 g_wohi[(size_t)DIM * KDIM];
__device__ __nv_bfloat16 g_wolo[(size_t)DIM * KDIM];
__device__ __nv_bfloat16 g_ahi[(size_t)MROWS * DIM];
__device__ __nv_bfloat16 g_alo[(size_t)MROWS * DIM];
// post-rope bf16 splits for attention
__device__ __nv_bfloat16 g_qhi[(size_t)MROWS * DIM];
__device__ __nv_bfloat16 g_qlo[(size_t)MROWS * DIM];
__device__ __nv_bfloat16 g_khi[(size_t)MROWS * KVDIM];
__device__ __nv_bfloat16 g_klo[(size_t)MROWS * KVDIM];
__device__ __nv_bfloat16 g_vhi[(size_t)MROWS * KVDIM];
__device__ __nv_bfloat16 g_vlo[(size_t)MROWS * KVDIM];

// ---------------- helpers ----------------------------------------------
__device__ __forceinline__ uint32_t smem_u32(const void* p) {
    uint32_t a;
    asm("{ .reg .u64 t; cvta.to.shared.u64 t, %1; cvt.u32.u64 %0, t; }"
        : "=r"(a) : "l"(p));
    return a;
}
__device__ __forceinline__ void ldsm4(uint32_t* d, uint32_t addr) {
    asm volatile("ldmatrix.sync.aligned.m8n8.x4.shared.b16 {%0,%1,%2,%3}, [%4];"
                 : "=r"(d[0]), "=r"(d[1]), "=r"(d[2]), "=r"(d[3]) : "r"(addr));
}
__device__ __forceinline__ void ldsm4t(uint32_t* d, uint32_t addr) {
    asm volatile("ldmatrix.sync.aligned.m8n8.x4.trans.shared.b16 {%0,%1,%2,%3}, [%4];"
                 : "=r"(d[0]), "=r"(d[1]), "=r"(d[2]), "=r"(d[3]) : "r"(addr));
}
__device__ __forceinline__ void mma16816(float* c, const uint32_t* a,
                                         uint32_t b0, uint32_t b1) {
    asm volatile(
        "mma.sync.aligned.m16n8k16.row.col.f32.bf16.bf16.f32 "
        "{%0,%1,%2,%3}, {%4,%5,%6,%7}, {%8,%9}, {%0,%1,%2,%3};"
        : "+f"(c[0]), "+f"(c[1]), "+f"(c[2]), "+f"(c[3])
        : "r"(a[0]), "r"(a[1]), "r"(a[2]), "r"(a[3]), "r"(b0), "r"(b1));
}
#define CP_ASYNC16(dst, src) \
    asm volatile("cp.async.cg.shared.global [%0], [%1], 16;" \
                 :: "r"(dst), "l"(src) : "memory")
#define CP_COMMIT()  asm volatile("cp.async.commit_group;" ::: "memory")
#define CP_WAIT1()   asm volatile("cp.async.wait_group 1;" ::: "memory")

// ---------------------------------------------------------------------------
// fp32 -> (bf16 hi, bf16 lo) split
// ---------------------------------------------------------------------------
__global__ void split_kernel(const float* __restrict__ src,
                             __nv_bfloat16* __restrict__ hi,
                             __nv_bfloat16* __restrict__ lo, int n)
{
    int i = blockIdx.x * blockDim.x + threadIdx.x;
    if (i < n) {
        float f = src[i];
        __nv_bfloat16 h = __float2bfloat16(f);
        hi[i] = h;
        lo[i] = __float2bfloat16(f - __bfloat162float(h));
    }
}

// ---------------------------------------------------------------------------
// GEMM: C = A * B^T via bf16x3 split, mma.sync.
// 128x128x32 tile, 8 warps. 3-buffer cp.async pipeline, ONE sync per chunk.
// ---------------------------------------------------------------------------
#define BM 128
#define BN 128
#define BK 32
#define PADC 40
#define SPLIT_BYTES (BM * PADC * 2)
#define STAGE_BYTES (4 * SPLIT_BYTES)      // 40960
#define GEMM_SMEM   (3 * STAGE_BYTES)      // 122880

__global__ void __launch_bounds__(256)
gemm_mma(const __nv_bfloat16* __restrict__ Ahi,
         const __nv_bfloat16* __restrict__ Alo,
         const __nv_bfloat16* __restrict__ Bhi,
         const __nv_bfloat16* __restrict__ Blo,
         float* __restrict__ C, int N)
{
    extern __shared__ char smem[];
    const int K = KDIM;
    const uint32_t sbase = smem_u32(smem);
    const int tid = threadIdx.x;
    const int wid = tid >> 5;
    const int lane = tid & 31;
    const int warp_m = wid >> 2;
    const int warp_n = wid & 3;
    const int bm = blockIdx.y * BM;
    const int bn = blockIdx.x * BN;
    const int NCH = K / BK;

    float acc[4][4][4];
#pragma unroll
    for (int i = 0; i < 4; i++)
#pragma unroll
        for (int j = 0; j < 4; j++)
#pragma unroll
            for (int r = 0; r < 4; r++) acc[i][j][r] = 0.f;

    const int a_row = lane & 15;
    const int a_col = (lane >> 4) * 8;
    const int b_row = ((lane >> 4) * 8) + (lane & 7);
    const int b_col = ((lane >> 3) & 1) * 8;

    auto load_stage = [&](int ch, int st) {
        if (ch < NCH) {
            const int kc = ch * BK;
            const uint32_t base = sbase + st * STAGE_BYTES;
#pragma unroll
            for (int i = 0; i < 8; i++) {
                int u = tid + i * 256;
                int isB   = u >> 10;
                int v     = u & 1023;
                int split = v >> 9;
                int idx   = v & 511;
                int row   = idx >> 2;
                int ck    = (idx & 3) * 8;
                const __nv_bfloat16* src;
                if (!isB) src = (split ? Alo : Ahi) + (size_t)(bm + row) * K + kc + ck;
                else      src = (split ? Blo : Bhi) + (size_t)(bn + row) * K + kc + ck;
                uint32_t dst = base + (uint32_t)((isB * 2 + split) * SPLIT_BYTES)
                             + (uint32_t)(row * PADC + ck) * 2;
                CP_ASYNC16(dst, src);
            }
        }
        CP_COMMIT();
    };

    // 3-buffer, 2-deep prefetch, one __syncthreads per chunk
    load_stage(0, 0);
    load_stage(1, 1);

    int buf = 0;           // buffer holding chunk ch
    int nbuf = 2;          // buffer to fill with chunk ch+2
    for (int ch = 0; ch < NCH; ch++) {
        CP_WAIT1();
        __syncthreads();
        // issue next loads into the buffer freed by iteration ch-1
        load_stage(ch + 2, nbuf);

        const uint32_t tb = sbase + buf * STAGE_BYTES;
#pragma unroll
        for (int ks = 0; ks < 2; ks++) {
            uint32_t afr[2][4][4];
#pragma unroll
            for (int s = 0; s < 2; s++)
#pragma unroll
                for (int mt = 0; mt < 4; mt++) {
                    uint32_t addr = tb + s * SPLIT_BYTES
                        + (uint32_t)((warp_m * 64 + mt * 16 + a_row) * PADC
                                     + ks * 16 + a_col) * 2;
                    ldsm4(afr[s][mt], addr);
                }
            uint32_t bfr[2][2][4];
#pragma unroll
            for (int s = 0; s < 2; s++)
#pragma unroll
                for (int np = 0; np < 2; np++) {
                    uint32_t addr = tb + (2 + s) * SPLIT_BYTES
                        + (uint32_t)((warp_n * 32 + np * 16 + b_row) * PADC
                                     + ks * 16 + b_col) * 2;
                    ldsm4(bfr[s][np], addr);
                }
#pragma unroll
            for (int mt = 0; mt < 4; mt++)
#pragma unroll
                for (int nt = 0; nt < 4; nt++) {
                    uint32_t bh0 = bfr[0][nt >> 1][(nt & 1) * 2];
                    uint32_t bh1 = bfr[0][nt >> 1][(nt & 1) * 2 + 1];
                    uint32_t bl0 = bfr[1][nt >> 1][(nt & 1) * 2];
                    uint32_t bl1 = bfr[1][nt >> 1][(nt & 1) * 2 + 1];
                    mma16816(acc[mt][nt], afr[0][mt], bh0, bh1);
                    mma16816(acc[mt][nt], afr[0][mt], bl0, bl1);
                    mma16816(acc[mt][nt], afr[1][mt], bh0, bh1);
                }
        }
        buf = (buf == 2) ? 0 : buf + 1;
        nbuf = (nbuf == 2) ? 0 : nbuf + 1;
    }

#pragma unroll
    for (int mt = 0; mt < 4; mt++)
#pragma unroll
        for (int nt = 0; nt < 4; nt++) {
            int row0 = bm + warp_m * 64 + mt * 16 + (lane >> 2);
            int col  = bn + warp_n * 32 + nt * 8 + (lane & 3) * 2;
            *(float2*)(C + (size_t)row0 * N + col) =
                make_float2(acc[mt][nt][0], acc[mt][nt][1]);
            *(float2*)(C + (size_t)(row0 + 8) * N + col) =
                make_float2(acc[mt][nt][2], acc[mt][nt][3]);
        }
}

// ---------------------------------------------------------------------------
// RoPE + bf16 hi/lo split: g_q -> (g_qhi, g_qlo), g_k -> (g_khi, g_klo)
// ---------------------------------------------------------------------------
__global__ void rope_split_kernel(const float* __restrict__ cosp,
                                  const float* __restrict__ sinp)
{
    int idx = blockIdx.x * blockDim.x + threadIdx.x;
    const int QP = MROWS * (DIM / 2);
    const int KP = MROWS * (KVDIM / 2);
    float2 v; float c, sn;
    __nv_bfloat16 *hi, *lo; size_t off;
    if (idx < QP) {
        int row = idx >> 11, col = idx & 2047;
        int s = row & (S_LEN - 1), i = col & 63;
        c = cosp[s * 64 + i]; sn = sinp[s * 64 + i];
        v = *((const float2*)(g_q + (size_t)row * DIM) + col);
        off = (size_t)row * DIM + 2 * col;
        hi = g_qhi; lo = g_qlo;
    } else if (idx < QP + KP) {
        int j = idx - QP;
        int row = j >> 9, col = j & 511;
        int s = row & (S_LEN - 1), i = col & 63;
        c = cosp[s * 64 + i]; sn = sinp[s * 64 + i];
        v = *((const float2*)(g_k + (size_t)row * KVDIM) + col);
        off = (size_t)row * KVDIM + 2 * col;
        hi = g_khi; lo = g_klo;
    } else return;
    float rx = v.x * c - v.y * sn;
    float ry = v.x * sn + v.y * c;
    __nv_bfloat162 h = __floats2bfloat162_rn(rx, ry);
    float lx = rx - __bfloat162float(h.x);
    float ly = ry - __bfloat162float(h.y);
    __nv_bfloat162 l = __floats2bfloat162_rn(lx, ly);
    *(__nv_bfloat162*)(hi + off) = h;
    *(__nv_bfloat162*)(lo + off) = l;
}

// ---------------------------------------------------------------------------
// Tensor-core causal flash attention (unchanged from round 4).
// ---------------------------------------------------------------------------
#define APAD   136
#define QSP    (128 * APAD * 2)
#define QBYTES (2 * QSP)
#define KVSP   (64 * APAD * 2)
#define ASTAGE (4 * KVSP)
#define ATTN_SMEM (QBYTES + 2 * ASTAGE)

__global__ void __launch_bounds__(256)
attn_mma()
{
    extern __shared__ char smem[];
    const uint32_t sbase = smem_u32(smem);
    const int tid = threadIdx.x;
    const int warp = tid >> 5;
    const int lane = tid & 31;
    const int qb = blockIdx.x;
    const int h  = blockIdx.y;
    const int b  = blockIdx.z;
    const int kvh = h >> 2;
    const int q0 = qb * 128;
    const int bs = b * S_LEN;
    const int ntiles = 2 * qb + 2;

    const __nv_bfloat16* khi_b = g_khi + (size_t)bs * KVDIM + kvh * HD;
    const __nv_bfloat16* klo_b = g_klo + (size_t)bs * KVDIM + kvh * HD;
    const __nv_bfloat16* vhi_b = g_vhi + (size_t)bs * KVDIM + kvh * HD;
    const __nv_bfloat16* vlo_b = g_vlo + (size_t)bs * KVDIM + kvh * HD;

    {
        const __nv_bfloat16* qhi_b = g_qhi + (size_t)(bs + q0) * DIM + h * HD;
        const __nv_bfloat16* qlo_b = g_qlo + (size_t)(bs + q0) * DIM + h * HD;
#pragma unroll
        for (int i = 0; i < 16; i++) {
            int u = tid + i * 256;
            int split = u >> 11;
            int idx = u & 2047;
            int row = idx >> 4, ck = idx & 15;
            const __nv_bfloat16* src = (split ? qlo_b : qhi_b)
                                     + (size_t)row * DIM + ck * 8;
            uint32_t dst = sbase + split * QSP + (uint32_t)(row * APAD + ck * 8) * 2;
            CP_ASYNC16(dst, src);
        }
    }

    auto load_kv = [&](int t, int st) {
        if (t < ntiles) {
            const int k0 = t * 64;
            const uint32_t base = sbase + QBYTES + st * ASTAGE;
            const __nv_bfloat16* srcs[4] = {khi_b, klo_b, vhi_b, vlo_b};
#pragma unroll
            for (int i = 0; i < 16; i++) {
                int u = tid + i * 256;
                int split = u >> 10;
                int idx = u & 1023;
                int row = idx >> 4, ck = idx & 15;
                const __nv_bfloat16* src = srcs[split]
                                         + (size_t)(k0 + row) * KVDIM + ck * 8;
                uint32_t dst = base + split * KVSP
                             + (uint32_t)(row * APAD + ck * 8) * 2;
                CP_ASYNC16(dst, src);
            }
        }
        CP_COMMIT();
    };

    load_kv(0, 0);
    load_kv(1, 1);

    const int r0 = lane >> 2;
    const int grow0 = q0 + warp * 16 + r0;
    const int grow1 = grow0 + 8;
    const int wmaxrow = q0 + warp * 16 + 15;
    const float scale = 0.08838834764831845f;

    float m0 = -1e30f, m1 = -1e30f, l0 = 0.f, l1 = 0.f;
    float oacc[16][4];
#pragma unroll
    for (int i = 0; i < 16; i++)
#pragma unroll
        for (int j = 0; j < 4; j++) oacc[i][j] = 0.f;

    const int qa_off = (warp * 16 + (lane & 15)) * APAD + (lane >> 4) * 8;
    const int kb_row = ((lane >> 4) * 8) + (lane & 7);
    const int kb_colh = ((lane >> 3) & 1) * 8;
    const int v_key = (lane & 7) + ((lane >> 3) & 1) * 8;
    const int v_hd  = (lane >> 4) * 8;

    for (int t = 0; t < ntiles; t++) {
        CP_WAIT1();
        __syncthreads();
        const int k0 = t * 64;
        const uint32_t kb = sbase + QBYTES + (t & 1) * ASTAGE;

        if (k0 <= wmaxrow) {
            float sacc[8][4];
#pragma unroll
            for (int i = 0; i < 8; i++)
#pragma unroll
                for (int j = 0; j < 4; j++) sacc[i][j] = 0.f;

#pragma unroll
            for (int ks = 0; ks < 8; ks++) {
                uint32_t qh[4], ql[4];
                uint32_t qaddr = sbase + (uint32_t)(qa_off + ks * 16) * 2;
                ldsm4(qh, qaddr);
                ldsm4(ql, qaddr + QSP);
#pragma unroll
                for (int np = 0; np < 4; np++) {
                    uint32_t kh[4], kl[4];
                    uint32_t kaddr = kb
                        + (uint32_t)((np * 16 + kb_row) * APAD + ks * 16 + kb_colh) * 2;
                    ldsm4(kh, kaddr);
                    ldsm4(kl, kaddr + KVSP);
#pragma unroll
                    for (int h2 = 0; h2 < 2; h2++) {
                        int nt = np * 2 + h2;
                        mma16816(sacc[nt], qh, kh[h2 * 2], kh[h2 * 2 + 1]);
                        mma16816(sacc[nt], qh, kl[h2 * 2], kl[h2 * 2 + 1]);
                        mma16816(sacc[nt], ql, kh[h2 * 2], kh[h2 * 2 + 1]);
                    }
                }
            }

            const bool domask = (t >= 2 * qb);
            float mx0 = -1e30f, mx1 = -1e30f;
#pragma unroll
            for (int nt = 0; nt < 8; nt++) {
                float s0 = sacc[nt][0] * scale;
                float s1 = sacc[nt][1] * scale;
                float s2 = sacc[nt][2] * scale;
                float s3 = sacc[nt][3] * scale;
                if (domask) {
                    int gc = k0 + nt * 8 + 2 * (lane & 3);
                    if (gc > grow0)     s0 = -1e30f;
                    if (gc + 1 > grow0) s1 = -1e30f;
                    if (gc > grow1)     s2 = -1e30f;
                    if (gc + 1 > grow1) s3 = -1e30f;
                }
                sacc[nt][0] = s0; sacc[nt][1] = s1;
                sacc[nt][2] = s2; sacc[nt][3] = s3;
                mx0 = fmaxf(mx0, fmaxf(s0, s1));
                mx1 = fmaxf(mx1, fmaxf(s2, s3));
            }
            mx0 = fmaxf(mx0, __shfl_xor_sync(0xffffffffu, mx0, 1));
            mx0 = fmaxf(mx0, __shfl_xor_sync(0xffffffffu, mx0, 2));
            mx1 = fmaxf(mx1, __shfl_xor_sync(0xffffffffu, mx1, 1));
            mx1 = fmaxf(mx1, __shfl_xor_sync(0xffffffffu, mx1, 2));
            float mn0 = fmaxf(m0, mx0), mn1 = fmaxf(m1, mx1);
            float c0 = __expf(m0 - mn0), c1 = __expf(m1 - mn1);
            m0 = mn0; m1 = mn1;
            l0 *= c0; l1 *= c1;
#pragma unroll
            for (int nt = 0; nt < 16; nt++) {
                oacc[nt][0] *= c0; oacc[nt][1] *= c0;
                oacc[nt][2] *= c1; oacc[nt][3] *= c1;
            }
#pragma unroll
            for (int nt = 0; nt < 8; nt++) {
                float p0 = __expf(sacc[nt][0] - m0);
                float p1 = __expf(sacc[nt][1] - m0);
                float p2 = __expf(sacc[nt][2] - m1);
                float p3 = __expf(sacc[nt][3] - m1);
                sacc[nt][0] = p0; sacc[nt][1] = p1;
                sacc[nt][2] = p2; sacc[nt][3] = p3;
                l0 += p0 + p1; l1 += p2 + p3;
            }

#pragma unroll
            for (int kc = 0; kc < 4; kc++) {
                uint32_t ph[4], pl[4];
#pragma unroll
                for (int half = 0; half < 2; half++) {
                    const float* pp = sacc[2 * kc + half];
                    __nv_bfloat162 h01 = __floats2bfloat162_rn(pp[0], pp[1]);
                    __nv_bfloat162 h23 = __floats2bfloat162_rn(pp[2], pp[3]);
                    ph[half * 2 + 0] = *(uint32_t*)&h01;
                    ph[half * 2 + 1] = *(uint32_t*)&h23;
                    __nv_bfloat162 r01 = __floats2bfloat162_rn(
                        pp[0] - __bfloat162float(h01.x),
                        pp[1] - __bfloat162float(h01.y));
                    __nv_bfloat162 r23 = __floats2bfloat162_rn(
                        pp[2] - __bfloat162float(h23.x),
                        pp[3] - __bfloat162float(h23.y));
                    pl[half * 2 + 0] = *(uint32_t*)&r01;
                    pl[half * 2 + 1] = *(uint32_t*)&r23;
                }
                uint32_t pha[4] = { ph[0], ph[1], ph[2], ph[3] };
                uint32_t pla[4] = { pl[0], pl[1], pl[2], pl[3] };
#pragma unroll
                for (int np = 0; np < 8; np++) {
                    uint32_t vh[4], vl[4];
                    uint32_t vaddr = kb + 2 * KVSP
                        + (uint32_t)((kc * 16 + v_key) * APAD + np * 16 + v_hd) * 2;
                    ldsm4t(vh, vaddr);
                    ldsm4t(vl, vaddr + KVSP);
                    mma16816(oacc[2 * np],     pha, vh[0], vh[1]);
                    mma16816(oacc[2 * np],     pha, vl[0], vl[1]);
                    mma16816(oacc[2 * np],     pla, vh[0], vh[1]);
                    mma16816(oacc[2 * np + 1], pha, vh[2], vh[3]);
                    mma16816(oacc[2 * np + 1], pha, vl[2], vl[3]);
                    mma16816(oacc[2 * np + 1], pla, vh[2], vh[3]);
                }
            }
        }
        __syncthreads();
        load_kv(t + 2, t & 1);
    }

    l0 += __shfl_xor_sync(0xffffffffu, l0, 1);
    l0 += __shfl_xor_sync(0xffffffffu, l0, 2);
    l1 += __shfl_xor_sync(0xffffffffu, l1, 1);
    l1 += __shfl_xor_sync(0xffffffffu, l1, 2);
    float inv0 = 1.f / l0, inv1 = 1.f / l1;

    size_t gr0 = (size_t)(bs + grow0);
    size_t gr1 = (size_t)(bs + grow1);
#pragma unroll
    for (int nt = 0; nt < 16; nt++) {
        int col = h * HD + nt * 8 + 2 * (lane & 3);
        float o0 = oacc[nt][0] * inv0, o1 = oacc[nt][1] * inv0;
        float o2 = oacc[nt][2] * inv1, o3 = oacc[nt][3] * inv1;
        __nv_bfloat162 h0 = __floats2bfloat162_rn(o0, o1);
        __nv_bfloat162 h1 = __floats2bfloat162_rn(o2, o3);
        __nv_bfloat162 e0 = __floats2bfloat162_rn(o0 - __bfloat162float(h0.x),
                                                  o1 - __bfloat162float(h0.y));
        __nv_bfloat162 e1 = __floats2bfloat162_rn(o2 - __bfloat162float(h1.x),
                                                  o3 - __bfloat162float(h1.y));
        *(__nv_bfloat162*)(g_ahi + gr0 * DIM + col) = h0;
        *(__nv_bfloat162*)(g_alo + gr0 * DIM + col) = e0;
        *(__nv_bfloat162*)(g_ahi + gr1 * DIM + col) = h1;
        *(__nv_bfloat162*)(g_alo + gr1 * DIM + col) = e1;
    }
}

// ---------------------------------------------------------------------------
extern "C" void kernel_launch(void* const* d_in, const int* in_sizes, int n_in,
                              void* d_out, int out_size)
{
    (void)in_sizes; (void)n_in; (void)out_size;
    const float* x  = (const float*)d_in[0];
    const float* wq = (const float*)d_in[1];
    const float* wk = (const float*)d_in[2];
    const float* wv = (const float*)d_in[3];
    const float* wo = (const float*)d_in[4];
    const float* fc = (const float*)d_in[5];
    const float* fs = (const float*)d_in[6];
    float* out = (float*)d_out;

    float *q, *k, *v;
    cudaGetSymbolAddress((void**)&q, g_q);
    cudaGetSymbolAddress((void**)&k, g_k);
    cudaGetSymbolAddress((void**)&v, g_v);

    __nv_bfloat16 *xhi, *xlo, *wqhi, *wqlo, *wkhi, *wklo, *wvhi, *wvlo,
                  *wohi, *wolo, *ahi, *alo, *vhi, *vlo;
    cudaGetSymbolAddress((void**)&xhi,  g_xhi);
    cudaGetSymbolAddress((void**)&xlo,  g_xlo);
    cudaGetSymbolAddress((void**)&wqhi, g_wqhi);
    cudaGetSymbolAddress((void**)&wqlo, g_wqlo);
    cudaGetSymbolAddress((void**)&wkhi, g_wkhi);
    cudaGetSymbolAddress((void**)&wklo, g_wklo);
    cudaGetSymbolAddress((void**)&wvhi, g_wvhi);
    cudaGetSymbolAddress((void**)&wvlo, g_wvlo);
    cudaGetSymbolAddress((void**)&wohi, g_wohi);
    cudaGetSymbolAddress((void**)&wolo, g_wolo);
    cudaGetSymbolAddress((void**)&ahi,  g_ahi);
    cudaGetSymbolAddress((void**)&alo,  g_alo);
    cudaGetSymbolAddress((void**)&vhi,  g_vhi);
    cudaGetSymbolAddress((void**)&vlo,  g_vlo);

    cudaFuncSetAttribute(gemm_mma,
                         cudaFuncAttributeMaxDynamicSharedMemorySize, GEMM_SMEM);
    cudaFuncSetAttribute(attn_mma,
                         cudaFuncAttributeMaxDynamicSharedMemorySize, ATTN_SMEM);

    const int NBIG = MROWS * KDIM;
    const int NKV  = KVDIM * KDIM;
    split_kernel<<<(NBIG + 255) / 256, 256>>>(x,  xhi,  xlo,  NBIG);
    split_kernel<<<(NBIG + 255) / 256, 256>>>(wq, wqhi, wqlo, NBIG);
    split_kernel<<<(NKV  + 255) / 256, 256>>>(wk, wkhi, wklo, NKV);
    split_kernel<<<(NKV  + 255) / 256, 256>>>(wv, wvhi, wvlo, NKV);
    split_kernel<<<(NBIG + 255) / 256, 256>>>(wo, wohi, wolo, NBIG);

    // QKV projections
    gemm_mma<<<dim3(DIM / BN,   MROWS / BM), 256, GEMM_SMEM>>>(
        xhi, xlo, wqhi, wqlo, q, DIM);
    gemm_mma<<<dim3(KVDIM / BN, MROWS / BM), 256, GEMM_SMEM>>>(
        xhi, xlo, wkhi, wklo, k, KVDIM);
    gemm_mma<<<dim3(KVDIM / BN, MROWS / BM), 256, GEMM_SMEM>>>(
        xhi, xlo, wvhi, wvlo, v, KVDIM);

    // RoPE + split Q,K ; split V
    const int total_pairs = MROWS * (DIM / 2) + MROWS * (KVDIM / 2);
    rope_split_kernel<<<(total_pairs + 255) / 256, 256>>>(fc, fs);
    const int NV = MROWS * KVDIM;
    split_kernel<<<(NV + 255) / 256, 256>>>(v, vhi, vlo, NV);

    // Tensor-core flash attention -> writes g_ahi/g_alo
    attn_mma<<<dim3(S_LEN / 128, NH, BATCH), 256, ATTN_SMEM>>>();

    // O projection
    gemm_mma<<<dim3(DIM / BN, MROWS / BM), 256, GEMM_SMEM>>>(
        ahi, alo, wohi, wolo, out, DIM);
}

// round 6
// speedup vs baseline: 1.1048x; 1.1048x over previous
#include <cuda_runtime.h>
#include <cuda_bf16.h>
#include <cstdint>

#define S_LEN   2048
#define BATCH   2
#define DIM     4096
#define NH      32
#define KVHEADS 8
#define HD      128
#define MROWS   (BATCH * S_LEN)     // 4096
#define KVDIM   (KVHEADS * HD)      // 1024
#define KDIM    4096

// ---------------- scratch (__device__ globals) ------------------------------
__device__ float g_q[(size_t)MROWS * DIM];
__device__ float g_k[(size_t)MROWS * KVDIM];
__device__ float g_v[(size_t)MROWS * KVDIM];

__device__ __nv_bfloat16 g_xhi[(size_t)MROWS * KDIM];
__device__ __nv_bfloat16 g_xlo[(size_t)MROWS * KDIM];
__device__ __nv_bfloat16 g_wqhi[(size_t)DIM * KDIM];
__device__ __nv_bfloat16 g_wqlo[(size_t)DIM * KDIM];
__device__ __nv_bfloat16 g_wkhi[(size_t)KVDIM * KDIM];
__device__ __nv_bfloat16 g_wklo[(size_t)KVDIM * KDIM];
__device__ __nv_bfloat16 g_wvhi[(size_t)KVDIM * KDIM];
__device__ __nv_bfloat16 g_wvlo[(size_t)KVDIM * KDIM];
__device__ __nv_bfloat16 g_wohi[(size_t)DIM * KDIM];
__device__ __nv_bfloat16 g_wolo[(size_t)DIM * KDIM];
__device__ __nv_bfloat16 g_ahi[(size_t)MROWS * DIM];
__device__ __nv_bfloat16 g_alo[(size_t)MROWS * DIM];
// post-rope bf16 splits for attention
__device__ __nv_bfloat16 g_qhi[(size_t)MROWS * DIM];
__device__ __nv_bfloat16 g_qlo[(size_t)MROWS * DIM];
__device__ __nv_bfloat16 g_khi[(size_t)MROWS * KVDIM];
__device__ __nv_bfloat16 g_klo[(size_t)MROWS * KVDIM];
__device__ __nv_bfloat16 g_vhi[(size_t)MROWS * KVDIM];
__device__ __nv_bfloat16 g_vlo[(size_t)MROWS * KVDIM];

// ---------------- helpers ----------------------------------------------
__device__ __forceinline__ uint32_t smem_u32(const void* p) {
    uint32_t a;
    asm("{ .reg .u64 t; cvta.to.shared.u64 t, %1; cvt.u32.u64 %0, t; }"
        : "=r"(a) : "l"(p));
    return a;
}
__device__ __forceinline__ void ldsm4(uint32_t* d, uint32_t addr) {
    asm volatile("ldmatrix.sync.aligned.m8n8.x4.shared.b16 {%0,%1,%2,%3}, [%4];"
                 : "=r"(d[0]), "=r"(d[1]), "=r"(d[2]), "=r"(d[3]) : "r"(addr));
}
__device__ __forceinline__ void ldsm4t(uint32_t* d, uint32_t addr) {
    asm volatile("ldmatrix.sync.aligned.m8n8.x4.trans.shared.b16 {%0,%1,%2,%3}, [%4];"
                 : "=r"(d[0]), "=r"(d[1]), "=r"(d[2]), "=r"(d[3]) : "r"(addr));
}
__device__ __forceinline__ void mma16816(float* c, const uint32_t* a,
                                         uint32_t b0, uint32_t b1) {
    asm volatile(
        "mma.sync.aligned.m16n8k16.row.col.f32.bf16.bf16.f32 "
        "{%0,%1,%2,%3}, {%4,%5,%6,%7}, {%8,%9}, {%0,%1,%2,%3};"
        : "+f"(c[0]), "+f"(c[1]), "+f"(c[2]), "+f"(c[3])
        : "r"(a[0]), "r"(a[1]), "r"(a[2]), "r"(a[3]), "r"(b0), "r"(b1));
}
#define CP_ASYNC16(dst, src) \
    asm volatile("cp.async.cg.shared.global [%0], [%1], 16;" \
                 :: "r"(dst), "l"(src) : "memory")
#define CP_COMMIT()  asm volatile("cp.async.commit_group;" ::: "memory")
#define CP_WAIT1()   asm volatile("cp.async.wait_group 1;" ::: "memory")

// ---------------------------------------------------------------------------
// fp32 -> (bf16 hi, bf16 lo) split
// ---------------------------------------------------------------------------
__global__ void split_kernel(const float* __restrict__ src,
                             __nv_bfloat16* __restrict__ hi,
                             __nv_bfloat16* __restrict__ lo, int n)
{
    int i = blockIdx.x * blockDim.x + threadIdx.x;
    if (i < n) {
        float f = src[i];
        __nv_bfloat16 h = __float2bfloat16(f);
        hi[i] = h;
        lo[i] = __float2bfloat16(f - __bfloat162float(h));
    }
}

// ---------------------------------------------------------------------------
// GEMM: C = A * B^T via bf16x3 split, mma.sync.
// 128x128x64 tile, 8 warps, round-4 loop order (wait -> compute -> load),
// double-buffered cp.async, BK=64 halves barrier count vs round 4.
// ---------------------------------------------------------------------------
#define BM 128
#define BN 128
#define BK 64
#define PADC 72
#define SPLIT_BYTES (BM * PADC * 2)        // 18432 per split tile
#define STAGE_BYTES (4 * SPLIT_BYTES)      // 73728
#define GEMM_SMEM   (2 * STAGE_BYTES)      // 147456

__global__ void __launch_bounds__(256)
gemm_mma(const __nv_bfloat16* __restrict__ Ahi,
         const __nv_bfloat16* __restrict__ Alo,
         const __nv_bfloat16* __restrict__ Bhi,
         const __nv_bfloat16* __restrict__ Blo,
         float* __restrict__ C, int N)
{
    extern __shared__ char smem[];
    const int K = KDIM;
    const uint32_t sbase = smem_u32(smem);
    const int tid = threadIdx.x;
    const int wid = tid >> 5;
    const int lane = tid & 31;
    const int warp_m = wid >> 2;
    const int warp_n = wid & 3;
    const int bm = blockIdx.y * BM;
    const int bn = blockIdx.x * BN;
    const int NCH = K / BK;            // 64

    float acc[4][4][4];
#pragma unroll
    for (int i = 0; i < 4; i++)
#pragma unroll
        for (int j = 0; j < 4; j++)
#pragma unroll
            for (int r = 0; r < 4; r++) acc[i][j][r] = 0.f;

    const int a_row = lane & 15;
    const int a_col = (lane >> 4) * 8;
    const int b_row = ((lane >> 4) * 8) + (lane & 7);
    const int b_col = ((lane >> 3) & 1) * 8;

    auto load_stage = [&](int ch, int st) {
        if (ch < NCH) {
            const int kc = ch * BK;
            const uint32_t base = sbase + st * STAGE_BYTES;
#pragma unroll
            for (int i = 0; i < 16; i++) {
                int u = tid + i * 256;          // 0..4095
                int isB   = u >> 11;
                int v     = u & 2047;
                int split = v >> 10;
                int idx   = v & 1023;
                int row   = idx >> 3;
                int ck    = (idx & 7) * 8;
                const __nv_bfloat16* src;
                if (!isB) src = (split ? Alo : Ahi) + (size_t)(bm + row) * K + kc + ck;
                else      src = (split ? Blo : Bhi) + (size_t)(bn + row) * K + kc + ck;
                uint32_t dst = base + (uint32_t)((isB * 2 + split) * SPLIT_BYTES)
                             + (uint32_t)(row * PADC + ck) * 2;
                CP_ASYNC16(dst, src);
            }
        }
        CP_COMMIT();
    };

    load_stage(0, 0);
    load_stage(1, 1);

    for (int ch = 0; ch < NCH; ch++) {
        const int st = ch & 1;
        CP_WAIT1();
        __syncthreads();
        const uint32_t tb = sbase + st * STAGE_BYTES;
#pragma unroll
        for (int ks = 0; ks < 4; ks++) {
            uint32_t afr[2][4][4];
#pragma unroll
            for (int s = 0; s < 2; s++)
#pragma unroll
                for (int mt = 0; mt < 4; mt++) {
                    uint32_t addr = tb + s * SPLIT_BYTES
                        + (uint32_t)((warp_m * 64 + mt * 16 + a_row) * PADC
                                     + ks * 16 + a_col) * 2;
                    ldsm4(afr[s][mt], addr);
                }
            uint32_t bfr[2][2][4];
#pragma unroll
            for (int s = 0; s < 2; s++)
#pragma unroll
                for (int np = 0; np < 2; np++) {
                    uint32_t addr = tb + (2 + s) * SPLIT_BYTES
                        + (uint32_t)((warp_n * 32 + np * 16 + b_row) * PADC
                                     + ks * 16 + b_col) * 2;
                    ldsm4(bfr[s][np], addr);
                }
#pragma unroll
            for (int mt = 0; mt < 4; mt++)
#pragma unroll
                for (int nt = 0; nt < 4; nt++) {
                    uint32_t bh0 = bfr[0][nt >> 1][(nt & 1) * 2];
                    uint32_t bh1 = bfr[0][nt >> 1][(nt & 1) * 2 + 1];
                    uint32_t bl0 = bfr[1][nt >> 1][(nt & 1) * 2];
                    uint32_t bl1 = bfr[1][nt >> 1][(nt & 1) * 2 + 1];
                    mma16816(acc[mt][nt], afr[0][mt], bh0, bh1);
                    mma16816(acc[mt][nt], afr[0][mt], bl0, bl1);
                    mma16816(acc[mt][nt], afr[1][mt], bh0, bh1);
                }
        }
        __syncthreads();
        load_stage(ch + 2, st);
    }

#pragma unroll
    for (int mt = 0; mt < 4; mt++)
#pragma unroll
        for (int nt = 0; nt < 4; nt++) {
            int row0 = bm + warp_m * 64 + mt * 16 + (lane >> 2);
            int col  = bn + warp_n * 32 + nt * 8 + (lane & 3) * 2;
            *(float2*)(C + (size_t)row0 * N + col) =
                make_float2(acc[mt][nt][0], acc[mt][nt][1]);
            *(float2*)(C + (size_t)(row0 + 8) * N + col) =
                make_float2(acc[mt][nt][2], acc[mt][nt][3]);
        }
}

// ---------------------------------------------------------------------------
// RoPE + bf16 hi/lo split: g_q -> (g_qhi, g_qlo), g_k -> (g_khi, g_klo)
// ---------------------------------------------------------------------------
__global__ void rope_split_kernel(const float* __restrict__ cosp,
                                  const float* __restrict__ sinp)
{
    int idx = blockIdx.x * blockDim.x + threadIdx.x;
    const int QP = MROWS * (DIM / 2);
    const int KP = MROWS * (KVDIM / 2);
    float2 v; float c, sn;
    __nv_bfloat16 *hi, *lo; size_t off;
    if (idx < QP) {
        int row = idx >> 11, col = idx & 2047;
        int s = row & (S_LEN - 1), i = col & 63;
        c = cosp[s * 64 + i]; sn = sinp[s * 64 + i];
        v = *((const float2*)(g_q + (size_t)row * DIM) + col);
        off = (size_t)row * DIM + 2 * col;
        hi = g_qhi; lo = g_qlo;
    } else if (idx < QP + KP) {
        int j = idx - QP;
        int row = j >> 9, col = j & 511;
        int s = row & (S_LEN - 1), i = col & 63;
        c = cosp[s * 64 + i]; sn = sinp[s * 64 + i];
        v = *((const float2*)(g_k + (size_t)row * KVDIM) + col);
        off = (size_t)row * KVDIM + 2 * col;
        hi = g_khi; lo = g_klo;
    } else return;
    float rx = v.x * c - v.y * sn;
    float ry = v.x * sn + v.y * c;
    __nv_bfloat162 h = __floats2bfloat162_rn(rx, ry);
    float lx = rx - __bfloat162float(h.x);
    float ly = ry - __bfloat162float(h.y);
    __nv_bfloat162 l = __floats2bfloat162_rn(lx, ly);
    *(__nv_bfloat162*)(hi + off) = h;
    *(__nv_bfloat162*)(lo + off) = l;
}

// ---------------------------------------------------------------------------
// Tensor-core causal flash attention (unchanged from round 4).
// ---------------------------------------------------------------------------
#define APAD   136
#define QSP    (128 * APAD * 2)
#define QBYTES (2 * QSP)
#define KVSP   (64 * APAD * 2)
#define ASTAGE (4 * KVSP)
#define ATTN_SMEM (QBYTES + 2 * ASTAGE)

__global__ void __launch_bounds__(256)
attn_mma()
{
    extern __shared__ char smem[];
    const uint32_t sbase = smem_u32(smem);
    const int tid = threadIdx.x;
    const int warp = tid >> 5;
    const int lane = tid & 31;
    const int qb = blockIdx.x;
    const int h  = blockIdx.y;
    const int b  = blockIdx.z;
    const int kvh = h >> 2;
    const int q0 = qb * 128;
    const int bs = b * S_LEN;
    const int ntiles = 2 * qb + 2;

    const __nv_bfloat16* khi_b = g_khi + (size_t)bs * KVDIM + kvh * HD;
    const __nv_bfloat16* klo_b = g_klo + (size_t)bs * KVDIM + kvh * HD;
    const __nv_bfloat16* vhi_b = g_vhi + (size_t)bs * KVDIM + kvh * HD;
    const __nv_bfloat16* vlo_b = g_vlo + (size_t)bs * KVDIM + kvh * HD;

    {
        const __nv_bfloat16* qhi_b = g_qhi + (size_t)(bs + q0) * DIM + h * HD;
        const __nv_bfloat16* qlo_b = g_qlo + (size_t)(bs + q0) * DIM + h * HD;
#pragma unroll
        for (int i = 0; i < 16; i++) {
            int u = tid + i * 256;
            int split = u >> 11;
            int idx = u & 2047;
            int row = idx >> 4, ck = idx & 15;
            const __nv_bfloat16* src = (split ? qlo_b : qhi_b)
                                     + (size_t)row * DIM + ck * 8;
            uint32_t dst = sbase + split * QSP + (uint32_t)(row * APAD + ck * 8) * 2;
            CP_ASYNC16(dst, src);
        }
    }

    auto load_kv = [&](int t, int st) {
        if (t < ntiles) {
            const int k0 = t * 64;
            const uint32_t base = sbase + QBYTES + st * ASTAGE;
            const __nv_bfloat16* srcs[4] = {khi_b, klo_b, vhi_b, vlo_b};
#pragma unroll
            for (int i = 0; i < 16; i++) {
                int u = tid + i * 256;
                int split = u >> 10;
                int idx = u & 1023;
                int row = idx >> 4, ck = idx & 15;
                const __nv_bfloat16* src = srcs[split]
                                         + (size_t)(k0 + row) * KVDIM + ck * 8;
                uint32_t dst = base + split * KVSP
                             + (uint32_t)(row * APAD + ck * 8) * 2;
                CP_ASYNC16(dst, src);
            }
        }
        CP_COMMIT();
    };

    load_kv(0, 0);
    load_kv(1, 1);

    const int r0 = lane >> 2;
    const int grow0 = q0 + warp * 16 + r0;
    const int grow1 = grow0 + 8;
    const int wmaxrow = q0 + warp * 16 + 15;
    const float scale = 0.08838834764831845f;

    float m0 = -1e30f, m1 = -1e30f, l0 = 0.f, l1 = 0.f;
    float oacc[16][4];
#pragma unroll
    for (int i = 0; i < 16; i++)
#pragma unroll
        for (int j = 0; j < 4; j++) oacc[i][j] = 0.f;

    const int qa_off = (warp * 16 + (lane & 15)) * APAD + (lane >> 4) * 8;
    const int kb_row = ((lane >> 4) * 8) + (lane & 7);
    const int kb_colh = ((lane >> 3) & 1) * 8;
    const int v_key = (lane & 7) + ((lane >> 3) & 1) * 8;
    const int v_hd  = (lane >> 4) * 8;

    for (int t = 0; t < ntiles; t++) {
        CP_WAIT1();
        __syncthreads();
        const int k0 = t * 64;
        const uint32_t kb = sbase + QBYTES + (t & 1) * ASTAGE;

        if (k0 <= wmaxrow) {
            float sacc[8][4];
#pragma unroll
            for (int i = 0; i < 8; i++)
#pragma unroll
                for (int j = 0; j < 4; j++) sacc[i][j] = 0.f;

#pragma unroll
            for (int ks = 0; ks < 8; ks++) {
                uint32_t qh[4], ql[4];
                uint32_t qaddr = sbase + (uint32_t)(qa_off + ks * 16) * 2;
                ldsm4(qh, qaddr);
                ldsm4(ql, qaddr + QSP);
#pragma unroll
                for (int np = 0; np < 4; np++) {
                    uint32_t kh[4], kl[4];
                    uint32_t kaddr = kb
                        + (uint32_t)((np * 16 + kb_row) * APAD + ks * 16 + kb_colh) * 2;
                    ldsm4(kh, kaddr);
                    ldsm4(kl, kaddr + KVSP);
#pragma unroll
                    for (int h2 = 0; h2 < 2; h2++) {
                        int nt = np * 2 + h2;
                        mma16816(sacc[nt], qh, kh[h2 * 2], kh[h2 * 2 + 1]);
                        mma16816(sacc[nt], qh, kl[h2 * 2], kl[h2 * 2 + 1]);
                        mma16816(sacc[nt], ql, kh[h2 * 2], kh[h2 * 2 + 1]);
                    }
                }
            }

            const bool domask = (t >= 2 * qb);
            float mx0 = -1e30f, mx1 = -1e30f;
#pragma unroll
            for (int nt = 0; nt < 8; nt++) {
                float s0 = sacc[nt][0] * scale;
                float s1 = sacc[nt][1] * scale;
                float s2 = sacc[nt][2] * scale;
                float s3 = sacc[nt][3] * scale;
                if (domask) {
                    int gc = k0 + nt * 8 + 2 * (lane & 3);
                    if (gc > grow0)     s0 = -1e30f;
                    if (gc + 1 > grow0) s1 = -1e30f;
                    if (gc > grow1)     s2 = -1e30f;
                    if (gc + 1 > grow1) s3 = -1e30f;
                }
                sacc[nt][0] = s0; sacc[nt][1] = s1;
                sacc[nt][2] = s2; sacc[nt][3] = s3;
                mx0 = fmaxf(mx0, fmaxf(s0, s1));
                mx1 = fmaxf(mx1, fmaxf(s2, s3));
            }
            mx0 = fmaxf(mx0, __shfl_xor_sync(0xffffffffu, mx0, 1));
            mx0 = fmaxf(mx0, __shfl_xor_sync(0xffffffffu, mx0, 2));
            mx1 = fmaxf(mx1, __shfl_xor_sync(0xffffffffu, mx1, 1));
            mx1 = fmaxf(mx1, __shfl_xor_sync(0xffffffffu, mx1, 2));
            float mn0 = fmaxf(m0, mx0), mn1 = fmaxf(m1, mx1);
            float c0 = __expf(m0 - mn0), c1 = __expf(m1 - mn1);
            m0 = mn0; m1 = mn1;
            l0 *= c0; l1 *= c1;
#pragma unroll
            for (int nt = 0; nt < 16; nt++) {
                oacc[nt][0] *= c0; oacc[nt][1] *= c0;
                oacc[nt][2] *= c1; oacc[nt][3] *= c1;
            }
#pragma unroll
            for (int nt = 0; nt < 8; nt++) {
                float p0 = __expf(sacc[nt][0] - m0);
                float p1 = __expf(sacc[nt][1] - m0);
                float p2 = __expf(sacc[nt][2] - m1);
                float p3 = __expf(sacc[nt][3] - m1);
                sacc[nt][0] = p0; sacc[nt][1] = p1;
                sacc[nt][2] = p2; sacc[nt][3] = p3;
                l0 += p0 + p1; l1 += p2 + p3;
            }

#pragma unroll
            for (int kc = 0; kc < 4; kc++) {
                uint32_t ph[4], pl[4];
#pragma unroll
                for (int half = 0; half < 2; half++) {
                    const float* pp = sacc[2 * kc + half];
                    __nv_bfloat162 h01 = __floats2bfloat162_rn(pp[0], pp[1]);
                    __nv_bfloat162 h23 = __floats2bfloat162_rn(pp[2], pp[3]);
                    ph[half * 2 + 0] = *(uint32_t*)&h01;
                    ph[half * 2 + 1] = *(uint32_t*)&h23;
                    __nv_bfloat162 r01 = __floats2bfloat162_rn(
                        pp[0] - __bfloat162float(h01.x),
                        pp[1] - __bfloat162float(h01.y));
                    __nv_bfloat162 r23 = __floats2bfloat162_rn(
                        pp[2] - __bfloat162float(h23.x),
                        pp[3] - __bfloat162float(h23.y));
                    pl[half * 2 + 0] = *(uint32_t*)&r01;
                    pl[half * 2 + 1] = *(uint32_t*)&r23;
                }
                uint32_t pha[4] = { ph[0], ph[1], ph[2], ph[3] };
                uint32_t pla[4] = { pl[0], pl[1], pl[2], pl[3] };
#pragma unroll
                for (int np = 0; np < 8; np++) {
                    uint32_t vh[4], vl[4];
                    uint32_t vaddr = kb + 2 * KVSP
                        + (uint32_t)((kc * 16 + v_key) * APAD + np * 16 + v_hd) * 2;
                    ldsm4t(vh, vaddr);
                    ldsm4t(vl, vaddr + KVSP);
                    mma16816(oacc[2 * np],     pha, vh[0], vh[1]);
                    mma16816(oacc[2 * np],     pha, vl[0], vl[1]);
                    mma16816(oacc[2 * np],     pla, vh[0], vh[1]);
                    mma16816(oacc[2 * np + 1], pha, vh[2], vh[3]);
                    mma16816(oacc[2 * np + 1], pha, vl[2], vl[3]);
                    mma16816(oacc[2 * np + 1], pla, vh[2], vh[3]);
                }
            }
        }
        __syncthreads();
        load_kv(t + 2, t & 1);
    }

    l0 += __shfl_xor_sync(0xffffffffu, l0, 1);
    l0 += __shfl_xor_sync(0xffffffffu, l0, 2);
    l1 += __shfl_xor_sync(0xffffffffu, l1, 1);
    l1 += __shfl_xor_sync(0xffffffffu, l1, 2);
    float inv0 = 1.f / l0, inv1 = 1.f / l1;

    size_t gr0 = (size_t)(bs + grow0);
    size_t gr1 = (size_t)(bs + grow1);
#pragma unroll
    for (int nt = 0; nt < 16; nt++) {
        int col = h * HD + nt * 8 + 2 * (lane & 3);
        float o0 = oacc[nt][0] * inv0, o1 = oacc[nt][1] * inv0;
        float o2 = oacc[nt][2] * inv1, o3 = oacc[nt][3] * inv1;
        __nv_bfloat162 h0 = __floats2bfloat162_rn(o0, o1);
        __nv_bfloat162 h1 = __floats2bfloat162_rn(o2, o3);
        __nv_bfloat162 e0 = __floats2bfloat162_rn(o0 - __bfloat162float(h0.x),
                                                  o1 - __bfloat162float(h0.y));
        __nv_bfloat162 e1 = __floats2bfloat162_rn(o2 - __bfloat162float(h1.x),
                                                  o3 - __bfloat162float(h1.y));
        *(__nv_bfloat162*)(g_ahi + gr0 * DIM + col) = h0;
        *(__nv_bfloat162*)(g_alo + gr0 * DIM + col) = e0;
        *(__nv_bfloat162*)(g_ahi + gr1 * DIM + col) = h1;
        *(__nv_bfloat162*)(g_alo + gr1 * DIM + col) = e1;
    }
}

// ---------------------------------------------------------------------------
extern "C" void kernel_launch(void* const* d_in, const int* in_sizes, int n_in,
                              void* d_out, int out_size)
{
    (void)in_sizes; (void)n_in; (void)out_size;
    const float* x  = (const float*)d_in[0];
    const float* wq = (const float*)d_in[1];
    const float* wk = (const float*)d_in[2];
    const float* wv = (const float*)d_in[3];
    const float* wo = (const float*)d_in[4];
    const float* fc = (const float*)d_in[5];
    const float* fs = (const float*)d_in[6];
    float* out = (float*)d_out;

    float *q, *k, *v;
    cudaGetSymbolAddress((void**)&q, g_q);
    cudaGetSymbolAddress((void**)&k, g_k);
    cudaGetSymbolAddress((void**)&v, g_v);

    __nv_bfloat16 *xhi, *xlo, *wqhi, *wqlo, *wkhi, *wklo, *wvhi, *wvlo,
                  *wohi, *wolo, *ahi, *alo, *vhi, *vlo;
    cudaGetSymbolAddress((void**)&xhi,  g_xhi);
    cudaGetSymbolAddress((void**)&xlo,  g_xlo);
    cudaGetSymbolAddress((void**)&wqhi, g_wqhi);
    cudaGetSymbolAddress((void**)&wqlo, g_wqlo);
    cudaGetSymbolAddress((void**)&wkhi, g_wkhi);
    cudaGetSymbolAddress((void**)&wklo, g_wklo);
    cudaGetSymbolAddress((void**)&wvhi, g_wvhi);
    cudaGetSymbolAddress((void**)&wvlo, g_wvlo);
    cudaGetSymbolAddress((void**)&wohi, g_wohi);
    cudaGetSymbolAddress((void**)&wolo, g_wolo);
    cudaGetSymbolAddress((void**)&ahi,  g_ahi);
    cudaGetSymbolAddress((void**)&alo,  g_alo);
    cudaGetSymbolAddress((void**)&vhi,  g_vhi);
    cudaGetSymbolAddress((void**)&vlo,  g_vlo);

    cudaFuncSetAttribute(gemm_mma,
                         cudaFuncAttributeMaxDynamicSharedMemorySize, GEMM_SMEM);
    cudaFuncSetAttribute(attn_mma,
                         cudaFuncAttributeMaxDynamicSharedMemorySize, ATTN_SMEM);

    const int NBIG = MROWS * KDIM;
    const int NKV  = KVDIM * KDIM;
    split_kernel<<<(NBIG + 255) / 256, 256>>>(x,  xhi,  xlo,  NBIG);
    split_kernel<<<(NBIG + 255) / 256, 256>>>(wq, wqhi, wqlo, NBIG);
    split_kernel<<<(NKV  + 255) / 256, 256>>>(wk, wkhi, wklo, NKV);
    split_kernel<<<(NKV  + 255) / 256, 256>>>(wv, wvhi, wvlo, NKV);
    split_kernel<<<(NBIG + 255) / 256, 256>>>(wo, wohi, wolo, NBIG);

    // QKV projections
    gemm_mma<<<dim3(DIM / BN,   MROWS / BM), 256, GEMM_SMEM>>>(
        xhi, xlo, wqhi, wqlo, q, DIM);
    gemm_mma<<<dim3(KVDIM / BN, MROWS / BM), 256, GEMM_SMEM>>>(
        xhi, xlo, wkhi, wklo, k, KVDIM);
    gemm_mma<<<dim3(KVDIM / BN, MROWS / BM), 256, GEMM_SMEM>>>(
        xhi, xlo, wvhi, wvlo, v, KVDIM);

    // RoPE + split Q,K ; split V
    const int total_pairs = MROWS * (DIM / 2) + MROWS * (KVDIM / 2);
    rope_split_kernel<<<(total_pairs + 255) / 256, 256>>>(fc, fs);
    const int NV = MROWS * KVDIM;
    split_kernel<<<(NV + 255) / 256, 256>>>(v, vhi, vlo, NV);

    // Tensor-core flash attention -> writes g_ahi/g_alo
    attn_mma<<<dim3(S_LEN / 128, NH, BATCH), 256, ATTN_SMEM>>>();

    // O projection
    gemm_mma<<<dim3(DIM / BN, MROWS / BM), 256, GEMM_SMEM>>>(
        ahi, alo, wohi, wolo, out, DIM);
}

// round 7
// speedup vs baseline: 1.4200x; 1.2853x over previous
#include <cuda_runtime.h>
#include <cuda_bf16.h>
#include <cuda_fp16.h>
#include <cstdint>

#define S_LEN   2048
#define BATCH   2
#define DIM     4096
#define NH      32
#define KVHEADS 8
#define HD      128
#define MROWS   (BATCH * S_LEN)     // 4096
#define KVDIM   (KVHEADS * HD)      // 1024
#define KDIM    4096

// ---------------- scratch (__device__ globals) ------------------------------
__device__ float g_q[(size_t)MROWS * DIM];
__device__ float g_k[(size_t)MROWS * KVDIM];
__device__ float g_v[(size_t)MROWS * KVDIM];

// fp16 GEMM operands
__device__ __half g_xh[(size_t)MROWS * KDIM];
__device__ __half g_xl[(size_t)MROWS * KDIM];
__device__ __half g_wqh[(size_t)DIM * KDIM];
__device__ __half g_wkh[(size_t)KVDIM * KDIM];
__device__ __half g_wvh[(size_t)KVDIM * KDIM];
__device__ __half g_woh[(size_t)DIM * KDIM];
__device__ __half g_ah[(size_t)MROWS * DIM];
__device__ __half g_al[(size_t)MROWS * DIM];
// post-rope bf16 splits for attention (bf16x3 path unchanged)
__device__ __nv_bfloat16 g_qhi[(size_t)MROWS * DIM];
__device__ __nv_bfloat16 g_qlo[(size_t)MROWS * DIM];
__device__ __nv_bfloat16 g_khi[(size_t)MROWS * KVDIM];
__device__ __nv_bfloat16 g_klo[(size_t)MROWS * KVDIM];
__device__ __nv_bfloat16 g_vhi[(size_t)MROWS * KVDIM];
__device__ __nv_bfloat16 g_vlo[(size_t)MROWS * KVDIM];

// ---------------- helpers ----------------------------------------------
__device__ __forceinline__ uint32_t smem_u32(const void* p) {
    uint32_t a;
    asm("{ .reg .u64 t; cvta.to.shared.u64 t, %1; cvt.u32.u64 %0, t; }"
        : "=r"(a) : "l"(p));
    return a;
}
__device__ __forceinline__ void ldsm4(uint32_t* d, uint32_t addr) {
    asm volatile("ldmatrix.sync.aligned.m8n8.x4.shared.b16 {%0,%1,%2,%3}, [%4];"
                 : "=r"(d[0]), "=r"(d[1]), "=r"(d[2]), "=r"(d[3]) : "r"(addr));
}
__device__ __forceinline__ void ldsm4t(uint32_t* d, uint32_t addr) {
    asm volatile("ldmatrix.sync.aligned.m8n8.x4.trans.shared.b16 {%0,%1,%2,%3}, [%4];"
                 : "=r"(d[0]), "=r"(d[1]), "=r"(d[2]), "=r"(d[3]) : "r"(addr));
}
// bf16 mma (attention)
__device__ __forceinline__ void mma16816(float* c, const uint32_t* a,
                                         uint32_t b0, uint32_t b1) {
    asm volatile(
        "mma.sync.aligned.m16n8k16.row.col.f32.bf16.bf16.f32 "
        "{%0,%1,%2,%3}, {%4,%5,%6,%7}, {%8,%9}, {%0,%1,%2,%3};"
        : "+f"(c[0]), "+f"(c[1]), "+f"(c[2]), "+f"(c[3])
        : "r"(a[0]), "r"(a[1]), "r"(a[2]), "r"(a[3]), "r"(b0), "r"(b1));
}
// fp16 mma (projection GEMMs)
__device__ __forceinline__ void mma16816h(float* c, const uint32_t* a,
                                          uint32_t b0, uint32_t b1) {
    asm volatile(
        "mma.sync.aligned.m16n8k16.row.col.f32.f16.f16.f32 "
        "{%0,%1,%2,%3}, {%4,%5,%6,%7}, {%8,%9}, {%0,%1,%2,%3};"
        : "+f"(c[0]), "+f"(c[1]), "+f"(c[2]), "+f"(c[3])
        : "r"(a[0]), "r"(a[1]), "r"(a[2]), "r"(a[3]), "r"(b0), "r"(b1));
}
#define CP_ASYNC16(dst, src) \
    asm volatile("cp.async.cg.shared.global [%0], [%1], 16;" \
                 :: "r"(dst), "l"(src) : "memory")
#define CP_COMMIT()  asm volatile("cp.async.commit_group;" ::: "memory")
#define CP_WAIT1()   asm volatile("cp.async.wait_group 1;" ::: "memory")

// ---------------------------------------------------------------------------
// fp32 -> (fp16 hi, fp16 lo) split  /  fp32 -> fp16 round
// ---------------------------------------------------------------------------
__global__ void split_half_kernel(const float* __restrict__ src,
                                  __half* __restrict__ hi,
                                  __half* __restrict__ lo, int n)
{
    int i = blockIdx.x * blockDim.x + threadIdx.x;
    if (i < n) {
        float f = src[i];
        __half h = __float2half_rn(f);
        hi[i] = h;
        lo[i] = __float2half_rn(f - __half2float(h));
    }
}
__global__ void round_half_kernel(const float* __restrict__ src,
                                  __half* __restrict__ dst, int n)
{
    int i = blockIdx.x * blockDim.x + threadIdx.x;
    if (i < n) dst[i] = __float2half_rn(src[i]);
}
// fp32 -> (bf16 hi, bf16 lo) split (for V, attention path)
__global__ void split_kernel(const float* __restrict__ src,
                             __nv_bfloat16* __restrict__ hi,
                             __nv_bfloat16* __restrict__ lo, int n)
{
    int i = blockIdx.x * blockDim.x + threadIdx.x;
    if (i < n) {
        float f = src[i];
        __nv_bfloat16 h = __float2bfloat16(f);
        hi[i] = h;
        lo[i] = __float2bfloat16(f - __bfloat162float(h));
    }
}

// ---------------------------------------------------------------------------
// GEMM: C[M,N] = (Ah+Al)[M,K] * Bh[N,K]^T, fp16 2-term, fp32 accum.
// 128x256 block tile, 8 warps (2x4), 64x64 warp tile, BK=64, double-buffered.
// ---------------------------------------------------------------------------
#define BM 128
#define BN 256
#define BK 64
#define PADC 72
#define A_SPL   (BM * PADC * 2)            // 18432 per A split tile
#define B_BYTES (BN * PADC * 2)            // 36864
#define STAGE_BYTES (2 * A_SPL + B_BYTES)  // 73728
#define GEMM_SMEM   (2 * STAGE_BYTES)      // 147456

__global__ void __launch_bounds__(256)
gemm_fp16x2(const __half* __restrict__ Ah,
            const __half* __restrict__ Al,
            const __half* __restrict__ Bh,
            float* __restrict__ C, int N)
{
    extern __shared__ char smem[];
    const int K = KDIM;
    const uint32_t sbase = smem_u32(smem);
    const int tid = threadIdx.x;
    const int wid = tid >> 5;
    const int lane = tid & 31;
    const int warp_m = wid >> 2;       // 0..1 : 64 rows
    const int warp_n = wid & 3;        // 0..3 : 64 cols
    const int bm = blockIdx.y * BM;
    const int bn = blockIdx.x * BN;
    const int NCH = K / BK;            // 64

    float acc[4][8][4];
#pragma unroll
    for (int i = 0; i < 4; i++)
#pragma unroll
        for (int j = 0; j < 8; j++)
#pragma unroll
            for (int r = 0; r < 4; r++) acc[i][j][r] = 0.f;

    const int a_row = lane & 15;
    const int a_col = (lane >> 4) * 8;
    const int b_row = ((lane >> 4) * 8) + (lane & 7);
    const int b_col = ((lane >> 3) & 1) * 8;

    auto load_stage = [&](int ch, int st) {
        if (ch < NCH) {
            const int kc = ch * BK;
            const uint32_t base = sbase + st * STAGE_BYTES;
#pragma unroll
            for (int i = 0; i < 16; i++) {
                int u = tid + i * 256;          // 0..4095
                uint32_t dst; const __half* src;
                if (u < 2048) {                 // A hi / A lo
                    int split = u >> 10;
                    int idx = u & 1023;
                    int row = idx >> 3, ck = (idx & 7) * 8;
                    src = (split ? Al : Ah) + (size_t)(bm + row) * K + kc + ck;
                    dst = base + split * A_SPL + (uint32_t)(row * PADC + ck) * 2;
                } else {                        // B
                    int idx = u - 2048;         // 0..2047
                    int row = idx >> 3, ck = (idx & 7) * 8;
                    src = Bh + (size_t)(bn + row) * K + kc + ck;
                    dst = base + 2 * A_SPL + (uint32_t)(row * PADC + ck) * 2;
                }
                CP_ASYNC16(dst, src);
            }
        }
        CP_COMMIT();
    };

    load_stage(0, 0);
    load_stage(1, 1);

    for (int ch = 0; ch < NCH; ch++) {
        const int st = ch & 1;
        CP_WAIT1();
        __syncthreads();
        const uint32_t tb = sbase + st * STAGE_BYTES;
#pragma unroll
        for (int ks = 0; ks < 4; ks++) {
            // A fragments: hi and lo, 4 m16 tiles
            uint32_t afr[2][4][4];
#pragma unroll
            for (int s = 0; s < 2; s++)
#pragma unroll
                for (int mt = 0; mt < 4; mt++) {
                    uint32_t addr = tb + s * A_SPL
                        + (uint32_t)((warp_m * 64 + mt * 16 + a_row) * PADC
                                     + ks * 16 + a_col) * 2;
                    ldsm4(afr[s][mt], addr);
                }
            // B fragments: 4 n16 groups (covering 64 cols)
#pragma unroll
            for (int np = 0; np < 4; np++) {
                uint32_t bfr[4];
                uint32_t addr = tb + 2 * A_SPL
                    + (uint32_t)((warp_n * 64 + np * 16 + b_row) * PADC
                                 + ks * 16 + b_col) * 2;
                ldsm4(bfr, addr);
#pragma unroll
                for (int h2 = 0; h2 < 2; h2++) {
                    int nt = np * 2 + h2;
#pragma unroll
                    for (int mt = 0; mt < 4; mt++) {
                        mma16816h(acc[mt][nt], afr[0][mt],
                                  bfr[h2 * 2], bfr[h2 * 2 + 1]);
                        mma16816h(acc[mt][nt], afr[1][mt],
                                  bfr[h2 * 2], bfr[h2 * 2 + 1]);
                    }
                }
            }
        }
        __syncthreads();
        load_stage(ch + 2, st);
    }

#pragma unroll
    for (int mt = 0; mt < 4; mt++)
#pragma unroll
        for (int nt = 0; nt < 8; nt++) {
            int row0 = bm + warp_m * 64 + mt * 16 + (lane >> 2);
            int col  = bn + warp_n * 64 + nt * 8 + (lane & 3) * 2;
            *(float2*)(C + (size_t)row0 * N + col) =
                make_float2(acc[mt][nt][0], acc[mt][nt][1]);
            *(float2*)(C + (size_t)(row0 + 8) * N + col) =
                make_float2(acc[mt][nt][2], acc[mt][nt][3]);
        }
}

// ---------------------------------------------------------------------------
// RoPE + bf16 hi/lo split: g_q -> (g_qhi, g_qlo), g_k -> (g_khi, g_klo)
// ---------------------------------------------------------------------------
__global__ void rope_split_kernel(const float* __restrict__ cosp,
                                  const float* __restrict__ sinp)
{
    int idx = blockIdx.x * blockDim.x + threadIdx.x;
    const int QP = MROWS * (DIM / 2);
    const int KP = MROWS * (KVDIM / 2);
    float2 v; float c, sn;
    __nv_bfloat16 *hi, *lo; size_t off;
    if (idx < QP) {
        int row = idx >> 11, col = idx & 2047;
        int s = row & (S_LEN - 1), i = col & 63;
        c = cosp[s * 64 + i]; sn = sinp[s * 64 + i];
        v = *((const float2*)(g_q + (size_t)row * DIM) + col);
        off = (size_t)row * DIM + 2 * col;
        hi = g_qhi; lo = g_qlo;
    } else if (idx < QP + KP) {
        int j = idx - QP;
        int row = j >> 9, col = j & 511;
        int s = row & (S_LEN - 1), i = col & 63;
        c = cosp[s * 64 + i]; sn = sinp[s * 64 + i];
        v = *((const float2*)(g_k + (size_t)row * KVDIM) + col);
        off = (size_t)row * KVDIM + 2 * col;
        hi = g_khi; lo = g_klo;
    } else return;
    float rx = v.x * c - v.y * sn;
    float ry = v.x * sn + v.y * c;
    __nv_bfloat162 h = __floats2bfloat162_rn(rx, ry);
    float lx = rx - __bfloat162float(h.x);
    float ly = ry - __bfloat162float(h.y);
    __nv_bfloat162 l = __floats2bfloat162_rn(lx, ly);
    *(__nv_bfloat162*)(hi + off) = h;
    *(__nv_bfloat162*)(lo + off) = l;
}

// ---------------------------------------------------------------------------
// Tensor-core causal flash attention (bf16x3; epilogue writes fp16 hi/lo).
// ---------------------------------------------------------------------------
#define APAD   136
#define QSP    (128 * APAD * 2)
#define QBYTES (2 * QSP)
#define KVSP   (64 * APAD * 2)
#define ASTAGE (4 * KVSP)
#define ATTN_SMEM (QBYTES + 2 * ASTAGE)

__global__ void __launch_bounds__(256)
attn_mma()
{
    extern __shared__ char smem[];
    const uint32_t sbase = smem_u32(smem);
    const int tid = threadIdx.x;
    const int warp = tid >> 5;
    const int lane = tid & 31;
    const int qb = blockIdx.x;
    const int h  = blockIdx.y;
    const int b  = blockIdx.z;
    const int kvh = h >> 2;
    const int q0 = qb * 128;
    const int bs = b * S_LEN;
    const int ntiles = 2 * qb + 2;

    const __nv_bfloat16* khi_b = g_khi + (size_t)bs * KVDIM + kvh * HD;
    const __nv_bfloat16* klo_b = g_klo + (size_t)bs * KVDIM + kvh * HD;
    const __nv_bfloat16* vhi_b = g_vhi + (size_t)bs * KVDIM + kvh * HD;
    const __nv_bfloat16* vlo_b = g_vlo + (size_t)bs * KVDIM + kvh * HD;

    {
        const __nv_bfloat16* qhi_b = g_qhi + (size_t)(bs + q0) * DIM + h * HD;
        const __nv_bfloat16* qlo_b = g_qlo + (size_t)(bs + q0) * DIM + h * HD;
#pragma unroll
        for (int i = 0; i < 16; i++) {
            int u = tid + i * 256;
            int split = u >> 11;
            int idx = u & 2047;
            int row = idx >> 4, ck = idx & 15;
            const __nv_bfloat16* src = (split ? qlo_b : qhi_b)
                                     + (size_t)row * DIM + ck * 8;
            uint32_t dst = sbase + split * QSP + (uint32_t)(row * APAD + ck * 8) * 2;
            CP_ASYNC16(dst, src);
        }
    }

    auto load_kv = [&](int t, int st) {
        if (t < ntiles) {
            const int k0 = t * 64;
            const uint32_t base = sbase + QBYTES + st * ASTAGE;
            const __nv_bfloat16* srcs[4] = {khi_b, klo_b, vhi_b, vlo_b};
#pragma unroll
            for (int i = 0; i < 16; i++) {
                int u = tid + i * 256;
                int split = u >> 10;
                int idx = u & 1023;
                int row = idx >> 4, ck = idx & 15;
                const __nv_bfloat16* src = srcs[split]
                                         + (size_t)(k0 + row) * KVDIM + ck * 8;
                uint32_t dst = base + split * KVSP
                             + (uint32_t)(row * APAD + ck * 8) * 2;
                CP_ASYNC16(dst, src);
            }
        }
        CP_COMMIT();
    };

    load_kv(0, 0);
    load_kv(1, 1);

    const int r0 = lane >> 2;
    const int grow0 = q0 + warp * 16 + r0;
    const int grow1 = grow0 + 8;
    const int wmaxrow = q0 + warp * 16 + 15;
    const float scale = 0.08838834764831845f;

    float m0 = -1e30f, m1 = -1e30f, l0 = 0.f, l1 = 0.f;
    float oacc[16][4];
#pragma unroll
    for (int i = 0; i < 16; i++)
#pragma unroll
        for (int j = 0; j < 4; j++) oacc[i][j] = 0.f;

    const int qa_off = (warp * 16 + (lane & 15)) * APAD + (lane >> 4) * 8;
    const int kb_row = ((lane >> 4) * 8) + (lane & 7);
    const int kb_colh = ((lane >> 3) & 1) * 8;
    const int v_key = (lane & 7) + ((lane >> 3) & 1) * 8;
    const int v_hd  = (lane >> 4) * 8;

    for (int t = 0; t < ntiles; t++) {
        CP_WAIT1();
        __syncthreads();
        const int k0 = t * 64;
        const uint32_t kb = sbase + QBYTES + (t & 1) * ASTAGE;

        if (k0 <= wmaxrow) {
            float sacc[8][4];
#pragma unroll
            for (int i = 0; i < 8; i++)
#pragma unroll
                for (int j = 0; j < 4; j++) sacc[i][j] = 0.f;

#pragma unroll
            for (int ks = 0; ks < 8; ks++) {
                uint32_t qh[4], ql[4];
                uint32_t qaddr = sbase + (uint32_t)(qa_off + ks * 16) * 2;
                ldsm4(qh, qaddr);
                ldsm4(ql, qaddr + QSP);
#pragma unroll
                for (int np = 0; np < 4; np++) {
                    uint32_t kh[4], kl[4];
                    uint32_t kaddr = kb
                        + (uint32_t)((np * 16 + kb_row) * APAD + ks * 16 + kb_colh) * 2;
                    ldsm4(kh, kaddr);
                    ldsm4(kl, kaddr + KVSP);
#pragma unroll
                    for (int h2 = 0; h2 < 2; h2++) {
                        int nt = np * 2 + h2;
                        mma16816(sacc[nt], qh, kh[h2 * 2], kh[h2 * 2 + 1]);
                        mma16816(sacc[nt], qh, kl[h2 * 2], kl[h2 * 2 + 1]);
                        mma16816(sacc[nt], ql, kh[h2 * 2], kh[h2 * 2 + 1]);
                    }
                }
            }

            const bool domask = (t >= 2 * qb);
            float mx0 = -1e30f, mx1 = -1e30f;
#pragma unroll
            for (int nt = 0; nt < 8; nt++) {
                float s0 = sacc[nt][0] * scale;
                float s1 = sacc[nt][1] * scale;
                float s2 = sacc[nt][2] * scale;
                float s3 = sacc[nt][3] * scale;
                if (domask) {
                    int gc = k0 + nt * 8 + 2 * (lane & 3);
                    if (gc > grow0)     s0 = -1e30f;
                    if (gc + 1 > grow0) s1 = -1e30f;
                    if (gc > grow1)     s2 = -1e30f;
                    if (gc + 1 > grow1) s3 = -1e30f;
                }
                sacc[nt][0] = s0; sacc[nt][1] = s1;
                sacc[nt][2] = s2; sacc[nt][3] = s3;
                mx0 = fmaxf(mx0, fmaxf(s0, s1));
                mx1 = fmaxf(mx1, fmaxf(s2, s3));
            }
            mx0 = fmaxf(mx0, __shfl_xor_sync(0xffffffffu, mx0, 1));
            mx0 = fmaxf(mx0, __shfl_xor_sync(0xffffffffu, mx0, 2));
            mx1 = fmaxf(mx1, __shfl_xor_sync(0xffffffffu, mx1, 1));
            mx1 = fmaxf(mx1, __shfl_xor_sync(0xffffffffu, mx1, 2));
            float mn0 = fmaxf(m0, mx0), mn1 = fmaxf(m1, mx1);
            float c0 = __expf(m0 - mn0), c1 = __expf(m1 - mn1);
            m0 = mn0; m1 = mn1;
            l0 *= c0; l1 *= c1;
#pragma unroll
            for (int nt = 0; nt < 16; nt++) {
                oacc[nt][0] *= c0; oacc[nt][1] *= c0;
                oacc[nt][2] *= c1; oacc[nt][3] *= c1;
            }
#pragma unroll
            for (int nt = 0; nt < 8; nt++) {
                float p0 = __expf(sacc[nt][0] - m0);
                float p1 = __expf(sacc[nt][1] - m0);
                float p2 = __expf(sacc[nt][2] - m1);
                float p3 = __expf(sacc[nt][3] - m1);
                sacc[nt][0] = p0; sacc[nt][1] = p1;
                sacc[nt][2] = p2; sacc[nt][3] = p3;
                l0 += p0 + p1; l1 += p2 + p3;
            }

#pragma unroll
            for (int kc = 0; kc < 4; kc++) {
                uint32_t ph[4], pl[4];
#pragma unroll
                for (int half = 0; half < 2; half++) {
                    const float* pp = sacc[2 * kc + half];
                    __nv_bfloat162 h01 = __floats2bfloat162_rn(pp[0], pp[1]);
                    __nv_bfloat162 h23 = __floats2bfloat162_rn(pp[2], pp[3]);
                    ph[half * 2 + 0] = *(uint32_t*)&h01;
                    ph[half * 2 + 1] = *(uint32_t*)&h23;
                    __nv_bfloat162 r01 = __floats2bfloat162_rn(
                        pp[0] - __bfloat162float(h01.x),
                        pp[1] - __bfloat162float(h01.y));
                    __nv_bfloat162 r23 = __floats2bfloat162_rn(
                        pp[2] - __bfloat162float(h23.x),
                        pp[3] - __bfloat162float(h23.y));
                    pl[half * 2 + 0] = *(uint32_t*)&r01;
                    pl[half * 2 + 1] = *(uint32_t*)&r23;
                }
                uint32_t pha[4] = { ph[0], ph[1], ph[2], ph[3] };
                uint32_t pla[4] = { pl[0], pl[1], pl[2], pl[3] };
#pragma unroll
                for (int np = 0; np < 8; np++) {
                    uint32_t vh[4], vl[4];
                    uint32_t vaddr = kb + 2 * KVSP
                        + (uint32_t)((kc * 16 + v_key) * APAD + np * 16 + v_hd) * 2;
                    ldsm4t(vh, vaddr);
                    ldsm4t(vl, vaddr + KVSP);
                    mma16816(oacc[2 * np],     pha, vh[0], vh[1]);
                    mma16816(oacc[2 * np],     pha, vl[0], vl[1]);
                    mma16816(oacc[2 * np],     pla, vh[0], vh[1]);
                    mma16816(oacc[2 * np + 1], pha, vh[2], vh[3]);
                    mma16816(oacc[2 * np + 1], pha, vl[2], vl[3]);
                    mma16816(oacc[2 * np + 1], pla, vh[2], vh[3]);
                }
            }
        }
        __syncthreads();
        load_kv(t + 2, t & 1);
    }

    l0 += __shfl_xor_sync(0xffffffffu, l0, 1);
    l0 += __shfl_xor_sync(0xffffffffu, l0, 2);
    l1 += __shfl_xor_sync(0xffffffffu, l1, 1);
    l1 += __shfl_xor_sync(0xffffffffu, l1, 2);
    float inv0 = 1.f / l0, inv1 = 1.f / l1;

    size_t gr0 = (size_t)(bs + grow0);
    size_t gr1 = (size_t)(bs + grow1);
#pragma unroll
    for (int nt = 0; nt < 16; nt++) {
        int col = h * HD + nt * 8 + 2 * (lane & 3);
        float o0 = oacc[nt][0] * inv0, o1 = oacc[nt][1] * inv0;
        float o2 = oacc[nt][2] * inv1, o3 = oacc[nt][3] * inv1;
        __half2 h0 = __floats2half2_rn(o0, o1);
        __half2 h1 = __floats2half2_rn(o2, o3);
        __half2 e0 = __floats2half2_rn(o0 - __half2float(__low2half(h0)),
                                       o1 - __half2float(__high2half(h0)));
        __half2 e1 = __floats2half2_rn(o2 - __half2float(__low2half(h1)),
                                       o3 - __half2float(__high2half(h1)));
        *(__half2*)(g_ah + gr0 * DIM + col) = h0;
        *(__half2*)(g_al + gr0 * DIM + col) = e0;
        *(__half2*)(g_ah + gr1 * DIM + col) = h1;
        *(__half2*)(g_al + gr1 * DIM + col) = e1;
    }
}

// ---------------------------------------------------------------------------
extern "C" void kernel_launch(void* const* d_in, const int* in_sizes, int n_in,
                              void* d_out, int out_size)
{
    (void)in_sizes; (void)n_in; (void)out_size;
    const float* x  = (const float*)d_in[0];
    const float* wq = (const float*)d_in[1];
    const float* wk = (const float*)d_in[2];
    const float* wv = (const float*)d_in[3];
    const float* wo = (const float*)d_in[4];
    const float* fc = (const float*)d_in[5];
    const float* fs = (const float*)d_in[6];
    float* out = (float*)d_out;

    float *q, *k, *v;
    cudaGetSymbolAddress((void**)&q, g_q);
    cudaGetSymbolAddress((void**)&k, g_k);
    cudaGetSymbolAddress((void**)&v, g_v);

    __half *xh, *xl, *wqh, *wkh, *wvh, *woh, *ah, *al;
    cudaGetSymbolAddress((void**)&xh,  g_xh);
    cudaGetSymbolAddress((void**)&xl,  g_xl);
    cudaGetSymbolAddress((void**)&wqh, g_wqh);
    cudaGetSymbolAddress((void**)&wkh, g_wkh);
    cudaGetSymbolAddress((void**)&wvh, g_wvh);
    cudaGetSymbolAddress((void**)&woh, g_woh);
    cudaGetSymbolAddress((void**)&ah,  g_ah);
    cudaGetSymbolAddress((void**)&al,  g_al);

    __nv_bfloat16 *vhi, *vlo;
    cudaGetSymbolAddress((void**)&vhi, g_vhi);
    cudaGetSymbolAddress((void**)&vlo, g_vlo);

    cudaFuncSetAttribute(gemm_fp16x2,
                         cudaFuncAttributeMaxDynamicSharedMemorySize, GEMM_SMEM);
    cudaFuncSetAttribute(attn_mma,
                         cudaFuncAttributeMaxDynamicSharedMemorySize, ATTN_SMEM);

    const int NBIG = MROWS * KDIM;
    const int NKV  = KVDIM * KDIM;
    split_half_kernel<<<(NBIG + 255) / 256, 256>>>(x, xh, xl, NBIG);
    round_half_kernel<<<(NBIG + 255) / 256, 256>>>(wq, wqh, NBIG);
    round_half_kernel<<<(NKV  + 255) / 256, 256>>>(wk, wkh, NKV);
    round_half_kernel<<<(NKV  + 255) / 256, 256>>>(wv, wvh, NKV);
    round_half_kernel<<<(NBIG + 255) / 256, 256>>>(wo, woh, NBIG);

    // QKV projections (fp16 2-term)
    gemm_fp16x2<<<dim3(DIM / BN,   MROWS / BM), 256, GEMM_SMEM>>>(
        xh, xl, wqh, q, DIM);
    gemm_fp16x2<<<dim3(KVDIM / BN, MROWS / BM), 256, GEMM_SMEM>>>(
        xh, xl, wkh, k, KVDIM);
    gemm_fp16x2<<<dim3(KVDIM / BN, MROWS / BM), 256, GEMM_SMEM>>>(
        xh, xl, wvh, v, KVDIM);

    // RoPE + split Q,K (bf16) ; split V (bf16)
    const int total_pairs = MROWS * (DIM / 2) + MROWS * (KVDIM / 2);
    rope_split_kernel<<<(total_pairs + 255) / 256, 256>>>(fc, fs);
    const int NV = MROWS * KVDIM;
    split_kernel<<<(NV + 255) / 256, 256>>>(v, vhi, vlo, NV);

    // Tensor-core flash attention -> writes g_ah/g_al (fp16 hi/lo)
    attn_mma<<<dim3(S_LEN / 128, NH, BATCH), 256, ATTN_SMEM>>>();

    // O projection (fp16 2-term)
    gemm_fp16x2<<<dim3(DIM / BN, MROWS / BM), 256, GEMM_SMEM>>>(
        ah, al, woh, out, DIM);
}

// round 8
// speedup vs baseline: 2.0781x; 1.4635x over previous
#include <cuda_runtime.h>
#include <cuda_bf16.h>
#include <cuda_fp16.h>
#include <cstdint>

#define S_LEN   2048
#define BATCH   2
#define DIM     4096
#define NH      32
#define KVHEADS 8
#define HD      128
#define MROWS   (BATCH * S_LEN)     // 4096
#define KVDIM   (KVHEADS * HD)      // 1024
#define KDIM    4096

// ---------------- scratch (__device__ globals) ------------------------------
__device__ float g_q[(size_t)MROWS * DIM];
__device__ float g_k[(size_t)MROWS * KVDIM];
__device__ float g_v[(size_t)MROWS * KVDIM];

// fp16 GEMM operands (single rounded term each)
__device__ __half g_xh[(size_t)MROWS * KDIM];
__device__ __half g_wqh[(size_t)DIM * KDIM];
__device__ __half g_wkh[(size_t)KVDIM * KDIM];
__device__ __half g_wvh[(size_t)KVDIM * KDIM];
__device__ __half g_woh[(size_t)DIM * KDIM];
__device__ __half g_ah[(size_t)MROWS * DIM];
// post-rope bf16 splits for attention (bf16x3 path unchanged)
__device__ __nv_bfloat16 g_qhi[(size_t)MROWS * DIM];
__device__ __nv_bfloat16 g_qlo[(size_t)MROWS * DIM];
__device__ __nv_bfloat16 g_khi[(size_t)MROWS * KVDIM];
__device__ __nv_bfloat16 g_klo[(size_t)MROWS * KVDIM];
__device__ __nv_bfloat16 g_vhi[(size_t)MROWS * KVDIM];
__device__ __nv_bfloat16 g_vlo[(size_t)MROWS * KVDIM];

// ---------------- helpers ----------------------------------------------
__device__ __forceinline__ uint32_t smem_u32(const void* p) {
    uint32_t a;
    asm("{ .reg .u64 t; cvta.to.shared.u64 t, %1; cvt.u32.u64 %0, t; }"
        : "=r"(a) : "l"(p));
    return a;
}
__device__ __forceinline__ void ldsm4(uint32_t* d, uint32_t addr) {
    asm volatile("ldmatrix.sync.aligned.m8n8.x4.shared.b16 {%0,%1,%2,%3}, [%4];"
                 : "=r"(d[0]), "=r"(d[1]), "=r"(d[2]), "=r"(d[3]) : "r"(addr));
}
__device__ __forceinline__ void ldsm4t(uint32_t* d, uint32_t addr) {
    asm volatile("ldmatrix.sync.aligned.m8n8.x4.trans.shared.b16 {%0,%1,%2,%3}, [%4];"
                 : "=r"(d[0]), "=r"(d[1]), "=r"(d[2]), "=r"(d[3]) : "r"(addr));
}
// bf16 mma (attention)
__device__ __forceinline__ void mma16816(float* c, const uint32_t* a,
                                         uint32_t b0, uint32_t b1) {
    asm volatile(
        "mma.sync.aligned.m16n8k16.row.col.f32.bf16.bf16.f32 "
        "{%0,%1,%2,%3}, {%4,%5,%6,%7}, {%8,%9}, {%0,%1,%2,%3};"
        : "+f"(c[0]), "+f"(c[1]), "+f"(c[2]), "+f"(c[3])
        : "r"(a[0]), "r"(a[1]), "r"(a[2]), "r"(a[3]), "r"(b0), "r"(b1));
}
// fp16 mma (projection GEMMs)
__device__ __forceinline__ void mma16816h(float* c, const uint32_t* a,
                                          uint32_t b0, uint32_t b1) {
    asm volatile(
        "mma.sync.aligned.m16n8k16.row.col.f32.f16.f16.f32 "
        "{%0,%1,%2,%3}, {%4,%5,%6,%7}, {%8,%9}, {%0,%1,%2,%3};"
        : "+f"(c[0]), "+f"(c[1]), "+f"(c[2]), "+f"(c[3])
        : "r"(a[0]), "r"(a[1]), "r"(a[2]), "r"(a[3]), "r"(b0), "r"(b1));
}
#define CP_ASYNC16(dst, src) \
    asm volatile("cp.async.cg.shared.global [%0], [%1], 16;" \
                 :: "r"(dst), "l"(src) : "memory")
#define CP_COMMIT()  asm volatile("cp.async.commit_group;" ::: "memory")
#define CP_WAIT1()   asm volatile("cp.async.wait_group 1;" ::: "memory")

// ---------------------------------------------------------------------------
// fp32 -> fp16 round ; fp32 -> (bf16 hi, bf16 lo) split (attention V path)
// ---------------------------------------------------------------------------
__global__ void round_half_kernel(const float* __restrict__ src,
                                  __half* __restrict__ dst, int n)
{
    int i = blockIdx.x * blockDim.x + threadIdx.x;
    if (i < n) dst[i] = __float2half_rn(src[i]);
}
__global__ void split_kernel(const float* __restrict__ src,
                             __nv_bfloat16* __restrict__ hi,
                             __nv_bfloat16* __restrict__ lo, int n)
{
    int i = blockIdx.x * blockDim.x + threadIdx.x;
    if (i < n) {
        float f = src[i];
        __nv_bfloat16 h = __float2bfloat16(f);
        hi[i] = h;
        lo[i] = __float2bfloat16(f - __bfloat162float(h));
    }
}

// ---------------------------------------------------------------------------
// GEMM: C[M,N] = Ah[M,K] * Bh[N,K]^T, single fp16 MMA, fp32 accum.
// 128x256 block tile, 8 warps (2x4), 64x64 warp tile, BK=64, double-buffered.
// ---------------------------------------------------------------------------
#define BM 128
#define BN 256
#define BK 64
#define PADC 72
#define A_BYTES (BM * PADC * 2)            // 18432
#define B_BYTES (BN * PADC * 2)            // 36864
#define STAGE_BYTES (A_BYTES + B_BYTES)    // 55296
#define GEMM_SMEM   (2 * STAGE_BYTES)      // 110592

__global__ void __launch_bounds__(256)
gemm_fp16x1(const __half* __restrict__ Ah,
            const __half* __restrict__ Bh,
            float* __restrict__ C, int N)
{
    extern __shared__ char smem[];
    const int K = KDIM;
    const uint32_t sbase = smem_u32(smem);
    const int tid = threadIdx.x;
    const int wid = tid >> 5;
    const int lane = tid & 31;
    const int warp_m = wid >> 2;       // 0..1 : 64 rows
    const int warp_n = wid & 3;        // 0..3 : 64 cols
    const int bm = blockIdx.y * BM;
    const int bn = blockIdx.x * BN;
    const int NCH = K / BK;            // 64

    float acc[4][8][4];
#pragma unroll
    for (int i = 0; i < 4; i++)
#pragma unroll
        for (int j = 0; j < 8; j++)
#pragma unroll
            for (int r = 0; r < 4; r++) acc[i][j][r] = 0.f;

    const int a_row = lane & 15;
    const int a_col = (lane >> 4) * 8;
    const int b_row = ((lane >> 4) * 8) + (lane & 7);
    const int b_col = ((lane >> 3) & 1) * 8;

    auto load_stage = [&](int ch, int st) {
        if (ch < NCH) {
            const int kc = ch * BK;
            const uint32_t base = sbase + st * STAGE_BYTES;
#pragma unroll
            for (int i = 0; i < 12; i++) {
                int u = tid + i * 256;          // 0..3071
                uint32_t dst; const __half* src;
                if (u < 1024) {                 // A (128 rows x 8 chunks)
                    int row = u >> 3, ck = (u & 7) * 8;
                    src = Ah + (size_t)(bm + row) * K + kc + ck;
                    dst = base + (uint32_t)(row * PADC + ck) * 2;
                } else {                        // B (256 rows x 8 chunks)
                    int idx = u - 1024;         // 0..2047
                    int row = idx >> 3, ck = (idx & 7) * 8;
                    src = Bh + (size_t)(bn + row) * K + kc + ck;
                    dst = base + A_BYTES + (uint32_t)(row * PADC + ck) * 2;
                }
                CP_ASYNC16(dst, src);
            }
        }
        CP_COMMIT();
    };

    load_stage(0, 0);
    load_stage(1, 1);

    for (int ch = 0; ch < NCH; ch++) {
        const int st = ch & 1;
        CP_WAIT1();
        __syncthreads();
        const uint32_t tb = sbase + st * STAGE_BYTES;
#pragma unroll
        for (int ks = 0; ks < 4; ks++) {
            uint32_t afr[4][4];
#pragma unroll
            for (int mt = 0; mt < 4; mt++) {
                uint32_t addr = tb
                    + (uint32_t)((warp_m * 64 + mt * 16 + a_row) * PADC
                                 + ks * 16 + a_col) * 2;
                ldsm4(afr[mt], addr);
            }
#pragma unroll
            for (int np = 0; np < 4; np++) {
                uint32_t bfr[4];
                uint32_t addr = tb + A_BYTES
                    + (uint32_t)((warp_n * 64 + np * 16 + b_row) * PADC
                                 + ks * 16 + b_col) * 2;
                ldsm4(bfr, addr);
#pragma unroll
                for (int h2 = 0; h2 < 2; h2++) {
                    int nt = np * 2 + h2;
#pragma unroll
                    for (int mt = 0; mt < 4; mt++)
                        mma16816h(acc[mt][nt], afr[mt],
                                  bfr[h2 * 2], bfr[h2 * 2 + 1]);
                }
            }
        }
        __syncthreads();
        load_stage(ch + 2, st);
    }

#pragma unroll
    for (int mt = 0; mt < 4; mt++)
#pragma unroll
        for (int nt = 0; nt < 8; nt++) {
            int row0 = bm + warp_m * 64 + mt * 16 + (lane >> 2);
            int col  = bn + warp_n * 64 + nt * 8 + (lane & 3) * 2;
            *(float2*)(C + (size_t)row0 * N + col) =
                make_float2(acc[mt][nt][0], acc[mt][nt][1]);
            *(float2*)(C + (size_t)(row0 + 8) * N + col) =
                make_float2(acc[mt][nt][2], acc[mt][nt][3]);
        }
}

// ---------------------------------------------------------------------------
// RoPE + bf16 hi/lo split: g_q -> (g_qhi, g_qlo), g_k -> (g_khi, g_klo)
// ---------------------------------------------------------------------------
__global__ void rope_split_kernel(const float* __restrict__ cosp,
                                  const float* __restrict__ sinp)
{
    int idx = blockIdx.x * blockDim.x + threadIdx.x;
    const int QP = MROWS * (DIM / 2);
    const int KP = MROWS * (KVDIM / 2);
    float2 v; float c, sn;
    __nv_bfloat16 *hi, *lo; size_t off;
    if (idx < QP) {
        int row = idx >> 11, col = idx & 2047;
        int s = row & (S_LEN - 1), i = col & 63;
        c = cosp[s * 64 + i]; sn = sinp[s * 64 + i];
        v = *((const float2*)(g_q + (size_t)row * DIM) + col);
        off = (size_t)row * DIM + 2 * col;
        hi = g_qhi; lo = g_qlo;
    } else if (idx < QP + KP) {
        int j = idx - QP;
        int row = j >> 9, col = j & 511;
        int s = row & (S_LEN - 1), i = col & 63;
        c = cosp[s * 64 + i]; sn = sinp[s * 64 + i];
        v = *((const float2*)(g_k + (size_t)row * KVDIM) + col);
        off = (size_t)row * KVDIM + 2 * col;
        hi = g_khi; lo = g_klo;
    } else return;
    float rx = v.x * c - v.y * sn;
    float ry = v.x * sn + v.y * c;
    __nv_bfloat162 h = __floats2bfloat162_rn(rx, ry);
    float lx = rx - __bfloat162float(h.x);
    float ly = ry - __bfloat162float(h.y);
    __nv_bfloat162 l = __floats2bfloat162_rn(lx, ly);
    *(__nv_bfloat162*)(hi + off) = h;
    *(__nv_bfloat162*)(lo + off) = l;
}

// ---------------------------------------------------------------------------
// Tensor-core causal flash attention (bf16x3; epilogue writes fp16 rounded).
// ---------------------------------------------------------------------------
#define APAD   136
#define QSP    (128 * APAD * 2)
#define QBYTES (2 * QSP)
#define KVSP   (64 * APAD * 2)
#define ASTAGE (4 * KVSP)
#define ATTN_SMEM (QBYTES + 2 * ASTAGE)

__global__ void __launch_bounds__(256)
attn_mma()
{
    extern __shared__ char smem[];
    const uint32_t sbase = smem_u32(smem);
    const int tid = threadIdx.x;
    const int warp = tid >> 5;
    const int lane = tid & 31;
    const int qb = blockIdx.x;
    const int h  = blockIdx.y;
    const int b  = blockIdx.z;
    const int kvh = h >> 2;
    const int q0 = qb * 128;
    const int bs = b * S_LEN;
    const int ntiles = 2 * qb + 2;

    const __nv_bfloat16* khi_b = g_khi + (size_t)bs * KVDIM + kvh * HD;
    const __nv_bfloat16* klo_b = g_klo + (size_t)bs * KVDIM + kvh * HD;
    const __nv_bfloat16* vhi_b = g_vhi + (size_t)bs * KVDIM + kvh * HD;
    const __nv_bfloat16* vlo_b = g_vlo + (size_t)bs * KVDIM + kvh * HD;

    {
        const __nv_bfloat16* qhi_b = g_qhi + (size_t)(bs + q0) * DIM + h * HD;
        const __nv_bfloat16* qlo_b = g_qlo + (size_t)(bs + q0) * DIM + h * HD;
#pragma unroll
        for (int i = 0; i < 16; i++) {
            int u = tid + i * 256;
            int split = u >> 11;
            int idx = u & 2047;
            int row = idx >> 4, ck = idx & 15;
            const __nv_bfloat16* src = (split ? qlo_b : qhi_b)
                                     + (size_t)row * DIM + ck * 8;
            uint32_t dst = sbase + split * QSP + (uint32_t)(row * APAD + ck * 8) * 2;
            CP_ASYNC16(dst, src);
        }
    }

    auto load_kv = [&](int t, int st) {
        if (t < ntiles) {
            const int k0 = t * 64;
            const uint32_t base = sbase + QBYTES + st * ASTAGE;
            const __nv_bfloat16* srcs[4] = {khi_b, klo_b, vhi_b, vlo_b};
#pragma unroll
            for (int i = 0; i < 16; i++) {
                int u = tid + i * 256;
                int split = u >> 10;
                int idx = u & 1023;
                int row = idx >> 4, ck = idx & 15;
                const __nv_bfloat16* src = srcs[split]
                                         + (size_t)(k0 + row) * KVDIM + ck * 8;
                uint32_t dst = base + split * KVSP
                             + (uint32_t)(row * APAD + ck * 8) * 2;
                CP_ASYNC16(dst, src);
            }
        }
        CP_COMMIT();
    };

    load_kv(0, 0);
    load_kv(1, 1);

    const int r0 = lane >> 2;
    const int grow0 = q0 + warp * 16 + r0;
    const int grow1 = grow0 + 8;
    const int wmaxrow = q0 + warp * 16 + 15;
    const float scale = 0.08838834764831845f;

    float m0 = -1e30f, m1 = -1e30f, l0 = 0.f, l1 = 0.f;
    float oacc[16][4];
#pragma unroll
    for (int i = 0; i < 16; i++)
#pragma unroll
        for (int j = 0; j < 4; j++) oacc[i][j] = 0.f;

    const int qa_off = (warp * 16 + (lane & 15)) * APAD + (lane >> 4) * 8;
    const int kb_row = ((lane >> 4) * 8) + (lane & 7);
    const int kb_colh = ((lane >> 3) & 1) * 8;
    const int v_key = (lane & 7) + ((lane >> 3) & 1) * 8;
    const int v_hd  = (lane >> 4) * 8;

    for (int t = 0; t < ntiles; t++) {
        CP_WAIT1();
        __syncthreads();
        const int k0 = t * 64;
        const uint32_t kb = sbase + QBYTES + (t & 1) * ASTAGE;

        if (k0 <= wmaxrow) {
            float sacc[8][4];
#pragma unroll
            for (int i = 0; i < 8; i++)
#pragma unroll
                for (int j = 0; j < 4; j++) sacc[i][j] = 0.f;

#pragma unroll
            for (int ks = 0; ks < 8; ks++) {
                uint32_t qh[4], ql[4];
                uint32_t qaddr = sbase + (uint32_t)(qa_off + ks * 16) * 2;
                ldsm4(qh, qaddr);
                ldsm4(ql, qaddr + QSP);
#pragma unroll
                for (int np = 0; np < 4; np++) {
                    uint32_t kh[4], kl[4];
                    uint32_t kaddr = kb
                        + (uint32_t)((np * 16 + kb_row) * APAD + ks * 16 + kb_colh) * 2;
                    ldsm4(kh, kaddr);
                    ldsm4(kl, kaddr + KVSP);
#pragma unroll
                    for (int h2 = 0; h2 < 2; h2++) {
                        int nt = np * 2 + h2;
                        mma16816(sacc[nt], qh, kh[h2 * 2], kh[h2 * 2 + 1]);
                        mma16816(sacc[nt], qh, kl[h2 * 2], kl[h2 * 2 + 1]);
                        mma16816(sacc[nt], ql, kh[h2 * 2], kh[h2 * 2 + 1]);
                    }
                }
            }

            const bool domask = (t >= 2 * qb);
            float mx0 = -1e30f, mx1 = -1e30f;
#pragma unroll
            for (int nt = 0; nt < 8; nt++) {
                float s0 = sacc[nt][0] * scale;
                float s1 = sacc[nt][1] * scale;
                float s2 = sacc[nt][2] * scale;
                float s3 = sacc[nt][3] * scale;
                if (domask) {
                    int gc = k0 + nt * 8 + 2 * (lane & 3);
                    if (gc > grow0)     s0 = -1e30f;
                    if (gc + 1 > grow0) s1 = -1e30f;
                    if (gc > grow1)     s2 = -1e30f;
                    if (gc + 1 > grow1) s3 = -1e30f;
                }
                sacc[nt][0] = s0; sacc[nt][1] = s1;
                sacc[nt][2] = s2; sacc[nt][3] = s3;
                mx0 = fmaxf(mx0, fmaxf(s0, s1));
                mx1 = fmaxf(mx1, fmaxf(s2, s3));
            }
            mx0 = fmaxf(mx0, __shfl_xor_sync(0xffffffffu, mx0, 1));
            mx0 = fmaxf(mx0, __shfl_xor_sync(0xffffffffu, mx0, 2));
            mx1 = fmaxf(mx1, __shfl_xor_sync(0xffffffffu, mx1, 1));
            mx1 = fmaxf(mx1, __shfl_xor_sync(0xffffffffu, mx1, 2));
            float mn0 = fmaxf(m0, mx0), mn1 = fmaxf(m1, mx1);
            float c0 = __expf(m0 - mn0), c1 = __expf(m1 - mn1);
            m0 = mn0; m1 = mn1;
            l0 *= c0; l1 *= c1;
#pragma unroll
            for (int nt = 0; nt < 16; nt++) {
                oacc[nt][0] *= c0; oacc[nt][1] *= c0;
                oacc[nt][2] *= c1; oacc[nt][3] *= c1;
            }
#pragma unroll
            for (int nt = 0; nt < 8; nt++) {
                float p0 = __expf(sacc[nt][0] - m0);
                float p1 = __expf(sacc[nt][1] - m0);
                float p2 = __expf(sacc[nt][2] - m1);
                float p3 = __expf(sacc[nt][3] - m1);
                sacc[nt][0] = p0; sacc[nt][1] = p1;
                sacc[nt][2] = p2; sacc[nt][3] = p3;
                l0 += p0 + p1; l1 += p2 + p3;
            }

#pragma unroll
            for (int kc = 0; kc < 4; kc++) {
                uint32_t ph[4], pl[4];
#pragma unroll
                for (int half = 0; half < 2; half++) {
                    const float* pp = sacc[2 * kc + half];
                    __nv_bfloat162 h01 = __floats2bfloat162_rn(pp[0], pp[1]);
                    __nv_bfloat162 h23 = __floats2bfloat162_rn(pp[2], pp[3]);
                    ph[half * 2 + 0] = *(uint32_t*)&h01;
                    ph[half * 2 + 1] = *(uint32_t*)&h23;
                    __nv_bfloat162 r01 = __floats2bfloat162_rn(
                        pp[0] - __bfloat162float(h01.x),
                        pp[1] - __bfloat162float(h01.y));
                    __nv_bfloat162 r23 = __floats2bfloat162_rn(
                        pp[2] - __bfloat162float(h23.x),
                        pp[3] - __bfloat162float(h23.y));
                    pl[half * 2 + 0] = *(uint32_t*)&r01;
                    pl[half * 2 + 1] = *(uint32_t*)&r23;
                }
                uint32_t pha[4] = { ph[0], ph[1], ph[2], ph[3] };
                uint32_t pla[4] = { pl[0], pl[1], pl[2], pl[3] };
#pragma unroll
                for (int np = 0; np < 8; np++) {
                    uint32_t vh[4], vl[4];
                    uint32_t vaddr = kb + 2 * KVSP
                        + (uint32_t)((kc * 16 + v_key) * APAD + np * 16 + v_hd) * 2;
                    ldsm4t(vh, vaddr);
                    ldsm4t(vl, vaddr + KVSP);
                    mma16816(oacc[2 * np],     pha, vh[0], vh[1]);
                    mma16816(oacc[2 * np],     pha, vl[0], vl[1]);
                    mma16816(oacc[2 * np],     pla, vh[0], vh[1]);
                    mma16816(oacc[2 * np + 1], pha, vh[2], vh[3]);
                    mma16816(oacc[2 * np + 1], pha, vl[2], vl[3]);
                    mma16816(oacc[2 * np + 1], pla, vh[2], vh[3]);
                }
            }
        }
        __syncthreads();
        load_kv(t + 2, t & 1);
    }

    l0 += __shfl_xor_sync(0xffffffffu, l0, 1);
    l0 += __shfl_xor_sync(0xffffffffu, l0, 2);
    l1 += __shfl_xor_sync(0xffffffffu, l1, 1);
    l1 += __shfl_xor_sync(0xffffffffu, l1, 2);
    float inv0 = 1.f / l0, inv1 = 1.f / l1;

    size_t gr0 = (size_t)(bs + grow0);
    size_t gr1 = (size_t)(bs + grow1);
#pragma unroll
    for (int nt = 0; nt < 16; nt++) {
        int col = h * HD + nt * 8 + 2 * (lane & 3);
        __half2 h0 = __floats2half2_rn(oacc[nt][0] * inv0, oacc[nt][1] * inv0);
        __half2 h1 = __floats2half2_rn(oacc[nt][2] * inv1, oacc[nt][3] * inv1);
        *(__half2*)(g_ah + gr0 * DIM + col) = h0;
        *(__half2*)(g_ah + gr1 * DIM + col) = h1;
    }
}

// ---------------------------------------------------------------------------
extern "C" void kernel_launch(void* const* d_in, const int* in_sizes, int n_in,
                              void* d_out, int out_size)
{
    (void)in_sizes; (void)n_in; (void)out_size;
    const float* x  = (const float*)d_in[0];
    const float* wq = (const float*)d_in[1];
    const float* wk = (const float*)d_in[2];
    const float* wv = (const float*)d_in[3];
    const float* wo = (const float*)d_in[4];
    const float* fc = (const float*)d_in[5];
    const float* fs = (const float*)d_in[6];
    float* out = (float*)d_out;

    float *q, *k, *v;
    cudaGetSymbolAddress((void**)&q, g_q);
    cudaGetSymbolAddress((void**)&k, g_k);
    cudaGetSymbolAddress((void**)&v, g_v);

    __half *xh, *wqh, *wkh, *wvh, *woh, *ah;
    cudaGetSymbolAddress((void**)&xh,  g_xh);
    cudaGetSymbolAddress((void**)&wqh, g_wqh);
    cudaGetSymbolAddress((void**)&wkh, g_wkh);
    cudaGetSymbolAddress((void**)&wvh, g_wvh);
    cudaGetSymbolAddress((void**)&woh, g_woh);
    cudaGetSymbolAddress((void**)&ah,  g_ah);

    __nv_bfloat16 *vhi, *vlo;
    cudaGetSymbolAddress((void**)&vhi, g_vhi);
    cudaGetSymbolAddress((void**)&vlo, g_vlo);

    cudaFuncSetAttribute(gemm_fp16x1,
                         cudaFuncAttributeMaxDynamicSharedMemorySize, GEMM_SMEM);
    cudaFuncSetAttribute(attn_mma,
                         cudaFuncAttributeMaxDynamicSharedMemorySize, ATTN_SMEM);

    const int NBIG = MROWS * KDIM;
    const int NKV  = KVDIM * KDIM;
    round_half_kernel<<<(NBIG + 255) / 256, 256>>>(x,  xh,  NBIG);
    round_half_kernel<<<(NBIG + 255) / 256, 256>>>(wq, wqh, NBIG);
    round_half_kernel<<<(NKV  + 255) / 256, 256>>>(wk, wkh, NKV);
    round_half_kernel<<<(NKV  + 255) / 256, 256>>>(wv, wvh, NKV);
    round_half_kernel<<<(NBIG + 255) / 256, 256>>>(wo, woh, NBIG);

    // QKV projections (fp16 single MMA)
    gemm_fp16x1<<<dim3(DIM / BN,   MROWS / BM), 256, GEMM_SMEM>>>(xh, wqh, q, DIM);
    gemm_fp16x1<<<dim3(KVDIM / BN, MROWS / BM), 256, GEMM_SMEM>>>(xh, wkh, k, KVDIM);
    gemm_fp16x1<<<dim3(KVDIM / BN, MROWS / BM), 256, GEMM_SMEM>>>(xh, wvh, v, KVDIM);

    // RoPE + split Q,K (bf16) ; split V (bf16)
    const int total_pairs = MROWS * (DIM / 2) + MROWS * (KVDIM / 2);
    rope_split_kernel<<<(total_pairs + 255) / 256, 256>>>(fc, fs);
    const int NV = MROWS * KVDIM;
    split_kernel<<<(NV + 255) / 256, 256>>>(v, vhi, vlo, NV);

    // Tensor-core flash attention -> writes g_ah (fp16 rounded)
    attn_mma<<<dim3(S_LEN / 128, NH, BATCH), 256, ATTN_SMEM>>>();

    // O projection (fp16 single MMA)
    gemm_fp16x1<<<dim3(DIM / BN, MROWS / BM), 256, GEMM_SMEM>>>(ah, woh, out, DIM);
}

// round 9
// speedup vs baseline: 2.5059x; 1.2058x over previous
#include <cuda_runtime.h>
#include <cuda_bf16.h>
#include <cuda_fp16.h>
#include <cstdint>

#define S_LEN   2048
#define BATCH   2
#define DIM     4096
#define NH      32
#define KVHEADS 8
#define HD      128
#define MROWS   (BATCH * S_LEN)     // 4096
#define KVDIM   (KVHEADS * HD)      // 1024
#define KDIM    4096

// ---------------- scratch (__device__ globals) ------------------------------
__device__ float g_q[(size_t)MROWS * DIM];
__device__ float g_k[(size_t)MROWS * KVDIM];
__device__ float g_v[(size_t)MROWS * KVDIM];

// fp16 GEMM operands (single rounded term each)
__device__ __half g_xh[(size_t)MROWS * KDIM];
__device__ __half g_wqh[(size_t)DIM * KDIM];
__device__ __half g_wkh[(size_t)KVDIM * KDIM];
__device__ __half g_wvh[(size_t)KVDIM * KDIM];
__device__ __half g_woh[(size_t)DIM * KDIM];
__device__ __half g_ah[(size_t)MROWS * DIM];
// post-rope fp16 operands for attention
__device__ __half g_q16[(size_t)MROWS * DIM];
__device__ __half g_k16[(size_t)MROWS * KVDIM];
__device__ __half g_v16[(size_t)MROWS * KVDIM];

// ---------------- helpers ----------------------------------------------
__device__ __forceinline__ uint32_t smem_u32(const void* p) {
    uint32_t a;
    asm("{ .reg .u64 t; cvta.to.shared.u64 t, %1; cvt.u32.u64 %0, t; }"
        : "=r"(a) : "l"(p));
    return a;
}
__device__ __forceinline__ void ldsm4(uint32_t* d, uint32_t addr) {
    asm volatile("ldmatrix.sync.aligned.m8n8.x4.shared.b16 {%0,%1,%2,%3}, [%4];"
                 : "=r"(d[0]), "=r"(d[1]), "=r"(d[2]), "=r"(d[3]) : "r"(addr));
}
__device__ __forceinline__ void ldsm4t(uint32_t* d, uint32_t addr) {
    asm volatile("ldmatrix.sync.aligned.m8n8.x4.trans.shared.b16 {%0,%1,%2,%3}, [%4];"
                 : "=r"(d[0]), "=r"(d[1]), "=r"(d[2]), "=r"(d[3]) : "r"(addr));
}
// fp16 mma
__device__ __forceinline__ void mma16816h(float* c, const uint32_t* a,
                                          uint32_t b0, uint32_t b1) {
    asm volatile(
        "mma.sync.aligned.m16n8k16.row.col.f32.f16.f16.f32 "
        "{%0,%1,%2,%3}, {%4,%5,%6,%7}, {%8,%9}, {%0,%1,%2,%3};"
        : "+f"(c[0]), "+f"(c[1]), "+f"(c[2]), "+f"(c[3])
        : "r"(a[0]), "r"(a[1]), "r"(a[2]), "r"(a[3]), "r"(b0), "r"(b1));
}
#define CP_ASYNC16(dst, src) \
    asm volatile("cp.async.cg.shared.global [%0], [%1], 16;" \
                 :: "r"(dst), "l"(src) : "memory")
#define CP_COMMIT()  asm volatile("cp.async.commit_group;" ::: "memory")
#define CP_WAIT1()   asm volatile("cp.async.wait_group 1;" ::: "memory")

// ---------------------------------------------------------------------------
// fp32 -> fp16 round
// ---------------------------------------------------------------------------
__global__ void round_half_kernel(const float* __restrict__ src,
                                  __half* __restrict__ dst, int n)
{
    int i = blockIdx.x * blockDim.x + threadIdx.x;
    if (i < n) dst[i] = __float2half_rn(src[i]);
}

// ---------------------------------------------------------------------------
// GEMM: C[M,N] = Ah[M,K] * Bh[N,K]^T, single fp16 MMA, fp32 accum.
// 128x256 block tile, 8 warps (2x4), 64x64 warp tile, BK=64, double-buffered.
// ---------------------------------------------------------------------------
#define BM 128
#define BN 256
#define BK 64
#define PADC 72
#define A_BYTES (BM * PADC * 2)            // 18432
#define B_BYTES (BN * PADC * 2)            // 36864
#define STAGE_BYTES (A_BYTES + B_BYTES)    // 55296
#define GEMM_SMEM   (2 * STAGE_BYTES)      // 110592

__global__ void __launch_bounds__(256)
gemm_fp16x1(const __half* __restrict__ Ah,
            const __half* __restrict__ Bh,
            float* __restrict__ C, int N)
{
    extern __shared__ char smem[];
    const int K = KDIM;
    const uint32_t sbase = smem_u32(smem);
    const int tid = threadIdx.x;
    const int wid = tid >> 5;
    const int lane = tid & 31;
    const int warp_m = wid >> 2;
    const int warp_n = wid & 3;
    const int bm = blockIdx.y * BM;
    const int bn = blockIdx.x * BN;
    const int NCH = K / BK;

    float acc[4][8][4];
#pragma unroll
    for (int i = 0; i < 4; i++)
#pragma unroll
        for (int j = 0; j < 8; j++)
#pragma unroll
            for (int r = 0; r < 4; r++) acc[i][j][r] = 0.f;

    const int a_row = lane & 15;
    const int a_col = (lane >> 4) * 8;
    const int b_row = ((lane >> 4) * 8) + (lane & 7);
    const int b_col = ((lane >> 3) & 1) * 8;

    auto load_stage = [&](int ch, int st) {
        if (ch < NCH) {
            const int kc = ch * BK;
            const uint32_t base = sbase + st * STAGE_BYTES;
#pragma unroll
            for (int i = 0; i < 12; i++) {
                int u = tid + i * 256;
                uint32_t dst; const __half* src;
                if (u < 1024) {
                    int row = u >> 3, ck = (u & 7) * 8;
                    src = Ah + (size_t)(bm + row) * K + kc + ck;
                    dst = base + (uint32_t)(row * PADC + ck) * 2;
                } else {
                    int idx = u - 1024;
                    int row = idx >> 3, ck = (idx & 7) * 8;
                    src = Bh + (size_t)(bn + row) * K + kc + ck;
                    dst = base + A_BYTES + (uint32_t)(row * PADC + ck) * 2;
                }
                CP_ASYNC16(dst, src);
            }
        }
        CP_COMMIT();
    };

    load_stage(0, 0);
    load_stage(1, 1);

    for (int ch = 0; ch < NCH; ch++) {
        const int st = ch & 1;
        CP_WAIT1();
        __syncthreads();
        const uint32_t tb = sbase + st * STAGE_BYTES;
#pragma unroll
        for (int ks = 0; ks < 4; ks++) {
            uint32_t afr[4][4];
#pragma unroll
            for (int mt = 0; mt < 4; mt++) {
                uint32_t addr = tb
                    + (uint32_t)((warp_m * 64 + mt * 16 + a_row) * PADC
                                 + ks * 16 + a_col) * 2;
                ldsm4(afr[mt], addr);
            }
#pragma unroll
            for (int np = 0; np < 4; np++) {
                uint32_t bfr[4];
                uint32_t addr = tb + A_BYTES
                    + (uint32_t)((warp_n * 64 + np * 16 + b_row) * PADC
                                 + ks * 16 + b_col) * 2;
                ldsm4(bfr, addr);
#pragma unroll
                for (int h2 = 0; h2 < 2; h2++) {
                    int nt = np * 2 + h2;
#pragma unroll
                    for (int mt = 0; mt < 4; mt++)
                        mma16816h(acc[mt][nt], afr[mt],
                                  bfr[h2 * 2], bfr[h2 * 2 + 1]);
                }
            }
        }
        __syncthreads();
        load_stage(ch + 2, st);
    }

#pragma unroll
    for (int mt = 0; mt < 4; mt++)
#pragma unroll
        for (int nt = 0; nt < 8; nt++) {
            int row0 = bm + warp_m * 64 + mt * 16 + (lane >> 2);
            int col  = bn + warp_n * 64 + nt * 8 + (lane & 3) * 2;
            *(float2*)(C + (size_t)row0 * N + col) =
                make_float2(acc[mt][nt][0], acc[mt][nt][1]);
            *(float2*)(C + (size_t)(row0 + 8) * N + col) =
                make_float2(acc[mt][nt][2], acc[mt][nt][3]);
        }
}

// ---------------------------------------------------------------------------
// RoPE + fp16 round: g_q -> g_q16, g_k -> g_k16
// ---------------------------------------------------------------------------
__global__ void rope_half_kernel(const float* __restrict__ cosp,
                                 const float* __restrict__ sinp)
{
    int idx = blockIdx.x * blockDim.x + threadIdx.x;
    const int QP = MROWS * (DIM / 2);
    const int KP = MROWS * (KVDIM / 2);
    float2 v; float c, sn;
    __half* dst; size_t off;
    if (idx < QP) {
        int row = idx >> 11, col = idx & 2047;
        int s = row & (S_LEN - 1), i = col & 63;
        c = cosp[s * 64 + i]; sn = sinp[s * 64 + i];
        v = *((const float2*)(g_q + (size_t)row * DIM) + col);
        off = (size_t)row * DIM + 2 * col;
        dst = g_q16;
    } else if (idx < QP + KP) {
        int j = idx - QP;
        int row = j >> 9, col = j & 511;
        int s = row & (S_LEN - 1), i = col & 63;
        c = cosp[s * 64 + i]; sn = sinp[s * 64 + i];
        v = *((const float2*)(g_k + (size_t)row * KVDIM) + col);
        off = (size_t)row * KVDIM + 2 * col;
        dst = g_k16;
    } else return;
    float rx = v.x * c - v.y * sn;
    float ry = v.x * sn + v.y * c;
    *(__half2*)(dst + off) = __floats2half2_rn(rx, ry);
}

// ---------------------------------------------------------------------------
// Tensor-core causal flash attention, single fp16 MMA per tile.
// Block: 128 q rows, 8 warps (16 rows each). K/V tiles of 64 keys,
// cp.async double-buffered. Writes g_ah (fp16).
// ---------------------------------------------------------------------------
#define APAD   136
#define QSP    (128 * APAD * 2)       // 34816
#define KVSP   (64 * APAD * 2)        // 17408
#define ASTAGE (2 * KVSP)             // 34816 (K + V)
#define ATTN_SMEM (QSP + 2 * ASTAGE)  // 104448

__global__ void __launch_bounds__(256)
attn_mma()
{
    extern __shared__ char smem[];
    const uint32_t sbase = smem_u32(smem);
    const int tid = threadIdx.x;
    const int warp = tid >> 5;
    const int lane = tid & 31;
    const int qb = blockIdx.x;
    const int h  = blockIdx.y;
    const int b  = blockIdx.z;
    const int kvh = h >> 2;
    const int q0 = qb * 128;
    const int bs = b * S_LEN;
    const int ntiles = 2 * qb + 2;

    const __half* k_b = g_k16 + (size_t)bs * KVDIM + kvh * HD;
    const __half* v_b = g_v16 + (size_t)bs * KVDIM + kvh * HD;

    // ---- Q load (async, joins group 0): 128x128 fp16 = 2048 chunks --------
    {
        const __half* q_b = g_q16 + (size_t)(bs + q0) * DIM + h * HD;
#pragma unroll
        for (int i = 0; i < 8; i++) {
            int u = tid + i * 256;           // 0..2047
            int row = u >> 4, ck = u & 15;
            const __half* src = q_b + (size_t)row * DIM + ck * 8;
            uint32_t dst = sbase + (uint32_t)(row * APAD + ck * 8) * 2;
            CP_ASYNC16(dst, src);
        }
    }

    auto load_kv = [&](int t, int st) {
        if (t < ntiles) {
            const int k0 = t * 64;
            const uint32_t base = sbase + QSP + st * ASTAGE;
#pragma unroll
            for (int i = 0; i < 8; i++) {
                int u = tid + i * 256;       // 0..2047
                int isV = u >> 10;
                int idx = u & 1023;
                int row = idx >> 4, ck = idx & 15;
                const __half* src = (isV ? v_b : k_b)
                                  + (size_t)(k0 + row) * KVDIM + ck * 8;
                uint32_t dst = base + isV * KVSP
                             + (uint32_t)(row * APAD + ck * 8) * 2;
                CP_ASYNC16(dst, src);
            }
        }
        CP_COMMIT();
    };

    load_kv(0, 0);
    load_kv(1, 1);

    const int r0 = lane >> 2;
    const int grow0 = q0 + warp * 16 + r0;
    const int grow1 = grow0 + 8;
    const int wmaxrow = q0 + warp * 16 + 15;
    const float scale = 0.08838834764831845f;

    float m0 = -1e30f, m1 = -1e30f, l0 = 0.f, l1 = 0.f;
    float oacc[16][4];
#pragma unroll
    for (int i = 0; i < 16; i++)
#pragma unroll
        for (int j = 0; j < 4; j++) oacc[i][j] = 0.f;

    const int qa_off = (warp * 16 + (lane & 15)) * APAD + (lane >> 4) * 8;
    const int kb_row = ((lane >> 4) * 8) + (lane & 7);
    const int kb_colh = ((lane >> 3) & 1) * 8;
    const int v_key = (lane & 7) + ((lane >> 3) & 1) * 8;
    const int v_hd  = (lane >> 4) * 8;

    for (int t = 0; t < ntiles; t++) {
        CP_WAIT1();
        __syncthreads();
        const int k0 = t * 64;
        const uint32_t kb = sbase + QSP + (t & 1) * ASTAGE;

        if (k0 <= wmaxrow) {
            // ---- S = Q K^T (single fp16 MMA) -------------------------------
            float sacc[8][4];
#pragma unroll
            for (int i = 0; i < 8; i++)
#pragma unroll
                for (int j = 0; j < 4; j++) sacc[i][j] = 0.f;

#pragma unroll
            for (int ks = 0; ks < 8; ks++) {
                uint32_t qfr[4];
                ldsm4(qfr, sbase + (uint32_t)(qa_off + ks * 16) * 2);
#pragma unroll
                for (int np = 0; np < 4; np++) {
                    uint32_t kfr[4];
                    uint32_t kaddr = kb
                        + (uint32_t)((np * 16 + kb_row) * APAD + ks * 16 + kb_colh) * 2;
                    ldsm4(kfr, kaddr);
                    mma16816h(sacc[np * 2],     qfr, kfr[0], kfr[1]);
                    mma16816h(sacc[np * 2 + 1], qfr, kfr[2], kfr[3]);
                }
            }

            // ---- scale + mask + online softmax -----------------------------
            const bool domask = (t >= 2 * qb);
            float mx0 = -1e30f, mx1 = -1e30f;
#pragma unroll
            for (int nt = 0; nt < 8; nt++) {
                float s0 = sacc[nt][0] * scale;
                float s1 = sacc[nt][1] * scale;
                float s2 = sacc[nt][2] * scale;
                float s3 = sacc[nt][3] * scale;
                if (domask) {
                    int gc = k0 + nt * 8 + 2 * (lane & 3);
                    if (gc > grow0)     s0 = -1e30f;
                    if (gc + 1 > grow0) s1 = -1e30f;
                    if (gc > grow1)     s2 = -1e30f;
                    if (gc + 1 > grow1) s3 = -1e30f;
                }
                sacc[nt][0] = s0; sacc[nt][1] = s1;
                sacc[nt][2] = s2; sacc[nt][3] = s3;
                mx0 = fmaxf(mx0, fmaxf(s0, s1));
                mx1 = fmaxf(mx1, fmaxf(s2, s3));
            }
            mx0 = fmaxf(mx0, __shfl_xor_sync(0xffffffffu, mx0, 1));
            mx0 = fmaxf(mx0, __shfl_xor_sync(0xffffffffu, mx0, 2));
            mx1 = fmaxf(mx1, __shfl_xor_sync(0xffffffffu, mx1, 1));
            mx1 = fmaxf(mx1, __shfl_xor_sync(0xffffffffu, mx1, 2));
            float mn0 = fmaxf(m0, mx0), mn1 = fmaxf(m1, mx1);
            float c0 = __expf(m0 - mn0), c1 = __expf(m1 - mn1);
            m0 = mn0; m1 = mn1;
            l0 *= c0; l1 *= c1;
#pragma unroll
            for (int nt = 0; nt < 16; nt++) {
                oacc[nt][0] *= c0; oacc[nt][1] *= c0;
                oacc[nt][2] *= c1; oacc[nt][3] *= c1;
            }
#pragma unroll
            for (int nt = 0; nt < 8; nt++) {
                float p0 = __expf(sacc[nt][0] - m0);
                float p1 = __expf(sacc[nt][1] - m0);
                float p2 = __expf(sacc[nt][2] - m1);
                float p3 = __expf(sacc[nt][3] - m1);
                sacc[nt][0] = p0; sacc[nt][1] = p1;
                sacc[nt][2] = p2; sacc[nt][3] = p3;
                l0 += p0 + p1; l1 += p2 + p3;
            }

            // ---- O += P V (single fp16 MMA) --------------------------------
#pragma unroll
            for (int kc = 0; kc < 4; kc++) {
                uint32_t ph[4];
#pragma unroll
                for (int half = 0; half < 2; half++) {
                    const float* pp = sacc[2 * kc + half];
                    __half2 h01 = __floats2half2_rn(pp[0], pp[1]);
                    __half2 h23 = __floats2half2_rn(pp[2], pp[3]);
                    ph[half * 2 + 0] = *(uint32_t*)&h01;
                    ph[half * 2 + 1] = *(uint32_t*)&h23;
                }
#pragma unroll
                for (int np = 0; np < 8; np++) {
                    uint32_t vfr[4];
                    uint32_t vaddr = kb + KVSP
                        + (uint32_t)((kc * 16 + v_key) * APAD + np * 16 + v_hd) * 2;
                    ldsm4t(vfr, vaddr);
                    mma16816h(oacc[2 * np],     ph, vfr[0], vfr[1]);
                    mma16816h(oacc[2 * np + 1], ph, vfr[2], vfr[3]);
                }
            }
        }
        __syncthreads();
        load_kv(t + 2, t & 1);
    }

    // ---- epilogue -----------------------------------------------------------
    l0 += __shfl_xor_sync(0xffffffffu, l0, 1);
    l0 += __shfl_xor_sync(0xffffffffu, l0, 2);
    l1 += __shfl_xor_sync(0xffffffffu, l1, 1);
    l1 += __shfl_xor_sync(0xffffffffu, l1, 2);
    float inv0 = 1.f / l0, inv1 = 1.f / l1;

    size_t gr0 = (size_t)(bs + grow0);
    size_t gr1 = (size_t)(bs + grow1);
#pragma unroll
    for (int nt = 0; nt < 16; nt++) {
        int col = h * HD + nt * 8 + 2 * (lane & 3);
        __half2 h0 = __floats2half2_rn(oacc[nt][0] * inv0, oacc[nt][1] * inv0);
        __half2 h1 = __floats2half2_rn(oacc[nt][2] * inv1, oacc[nt][3] * inv1);
        *(__half2*)(g_ah + gr0 * DIM + col) = h0;
        *(__half2*)(g_ah + gr1 * DIM + col) = h1;
    }
}

// ---------------------------------------------------------------------------
extern "C" void kernel_launch(void* const* d_in, const int* in_sizes, int n_in,
                              void* d_out, int out_size)
{
    (void)in_sizes; (void)n_in; (void)out_size;
    const float* x  = (const float*)d_in[0];
    const float* wq = (const float*)d_in[1];
    const float* wk = (const float*)d_in[2];
    const float* wv = (const float*)d_in[3];
    const float* wo = (const float*)d_in[4];
    const float* fc = (const float*)d_in[5];
    const float* fs = (const float*)d_in[6];
    float* out = (float*)d_out;

    float *q, *k, *v;
    cudaGetSymbolAddress((void**)&q, g_q);
    cudaGetSymbolAddress((void**)&k, g_k);
    cudaGetSymbolAddress((void**)&v, g_v);

    __half *xh, *wqh, *wkh, *wvh, *woh, *ah, *v16;
    cudaGetSymbolAddress((void**)&xh,  g_xh);
    cudaGetSymbolAddress((void**)&wqh, g_wqh);
    cudaGetSymbolAddress((void**)&wkh, g_wkh);
    cudaGetSymbolAddress((void**)&wvh, g_wvh);
    cudaGetSymbolAddress((void**)&woh, g_woh);
    cudaGetSymbolAddress((void**)&ah,  g_ah);
    cudaGetSymbolAddress((void**)&v16, g_v16);

    cudaFuncSetAttribute(gemm_fp16x1,
                         cudaFuncAttributeMaxDynamicSharedMemorySize, GEMM_SMEM);
    cudaFuncSetAttribute(attn_mma,
                         cudaFuncAttributeMaxDynamicSharedMemorySize, ATTN_SMEM);

    const int NBIG = MROWS * KDIM;
    const int NKV  = KVDIM * KDIM;
    round_half_kernel<<<(NBIG + 255) / 256, 256>>>(x,  xh,  NBIG);
    round_half_kernel<<<(NBIG + 255) / 256, 256>>>(wq, wqh, NBIG);
    round_half_kernel<<<(NKV  + 255) / 256, 256>>>(wk, wkh, NKV);
    round_half_kernel<<<(NKV  + 255) / 256, 256>>>(wv, wvh, NKV);
    round_half_kernel<<<(NBIG + 255) / 256, 256>>>(wo, woh, NBIG);

    // QKV projections (fp16 single MMA)
    gemm_fp16x1<<<dim3(DIM / BN,   MROWS / BM), 256, GEMM_SMEM>>>(xh, wqh, q, DIM);
    gemm_fp16x1<<<dim3(KVDIM / BN, MROWS / BM), 256, GEMM_SMEM>>>(xh, wkh, k, KVDIM);
    gemm_fp16x1<<<dim3(KVDIM / BN, MROWS / BM), 256, GEMM_SMEM>>>(xh, wvh, v, KVDIM);

    // RoPE -> fp16 Q,K ; round V -> fp16
    const int total_pairs = MROWS * (DIM / 2) + MROWS * (KVDIM / 2);
    rope_half_kernel<<<(total_pairs + 255) / 256, 256>>>(fc, fs);
    const int NV = MROWS * KVDIM;
    round_half_kernel<<<(NV + 255) / 256, 256>>>(v, v16, NV);

    // Tensor-core flash attention (fp16) -> writes g_ah
    attn_mma<<<dim3(S_LEN / 128, NH, BATCH), 256, ATTN_SMEM>>>();

    // O projection (fp16 single MMA)
    gemm_fp16x1<<<dim3(DIM / BN, MROWS / BM), 256, GEMM_SMEM>>>(ah, woh, out, DIM);
}

// round 10
// speedup vs baseline: 2.7194x; 1.0852x over previous
#include <cuda_runtime.h>
#include <cuda_bf16.h>
#include <cuda_fp16.h>
#include <cstdint>

#define S_LEN   2048
#define BATCH   2
#define DIM     4096
#define NH      32
#define KVHEADS 8
#define HD      128
#define MROWS   (BATCH * S_LEN)     // 4096
#define KVDIM   (KVHEADS * HD)      // 1024
#define KDIM    4096

// ---------------- scratch (__device__ globals) ------------------------------
__device__ __half g_xh[(size_t)MROWS * KDIM];
__device__ __half g_wqh[(size_t)DIM * KDIM];
__device__ __half g_wkh[(size_t)KVDIM * KDIM];
__device__ __half g_wvh[(size_t)KVDIM * KDIM];
__device__ __half g_woh[(size_t)DIM * KDIM];
__device__ __half g_ah[(size_t)MROWS * DIM];
// post-rope fp16 operands for attention
__device__ __half g_q16[(size_t)MROWS * DIM];
__device__ __half g_k16[(size_t)MROWS * KVDIM];
__device__ __half g_v16[(size_t)MROWS * KVDIM];

// ---------------- helpers ----------------------------------------------
__device__ __forceinline__ uint32_t smem_u32(const void* p) {
    uint32_t a;
    asm("{ .reg .u64 t; cvta.to.shared.u64 t, %1; cvt.u32.u64 %0, t; }"
        : "=r"(a) : "l"(p));
    return a;
}
__device__ __forceinline__ void ldsm4(uint32_t* d, uint32_t addr) {
    asm volatile("ldmatrix.sync.aligned.m8n8.x4.shared.b16 {%0,%1,%2,%3}, [%4];"
                 : "=r"(d[0]), "=r"(d[1]), "=r"(d[2]), "=r"(d[3]) : "r"(addr));
}
__device__ __forceinline__ void ldsm4t(uint32_t* d, uint32_t addr) {
    asm volatile("ldmatrix.sync.aligned.m8n8.x4.trans.shared.b16 {%0,%1,%2,%3}, [%4];"
                 : "=r"(d[0]), "=r"(d[1]), "=r"(d[2]), "=r"(d[3]) : "r"(addr));
}
__device__ __forceinline__ void mma16816h(float* c, const uint32_t* a,
                                          uint32_t b0, uint32_t b1) {
    asm volatile(
        "mma.sync.aligned.m16n8k16.row.col.f32.f16.f16.f32 "
        "{%0,%1,%2,%3}, {%4,%5,%6,%7}, {%8,%9}, {%0,%1,%2,%3};"
        : "+f"(c[0]), "+f"(c[1]), "+f"(c[2]), "+f"(c[3])
        : "r"(a[0]), "r"(a[1]), "r"(a[2]), "r"(a[3]), "r"(b0), "r"(b1));
}
#define CP_ASYNC16(dst, src) \
    asm volatile("cp.async.cg.shared.global [%0], [%1], 16;" \
                 :: "r"(dst), "l"(src) : "memory")
#define CP_COMMIT()  asm volatile("cp.async.commit_group;" ::: "memory")
#define CP_WAIT1()   asm volatile("cp.async.wait_group 1;" ::: "memory")

// ---------------------------------------------------------------------------
// One fused fp32 -> fp16 round over all five operand tensors (float4 vec).
// Segment sizes are multiples of 1024, so each 4-elem unit is segment-pure.
// ---------------------------------------------------------------------------
__global__ void round_all_kernel(const float* __restrict__ x,
                                 const float* __restrict__ wq,
                                 const float* __restrict__ wk,
                                 const float* __restrict__ wv,
                                 const float* __restrict__ wo)
{
    const size_t NB = (size_t)MROWS * KDIM;   // 16777216
    const size_t NK = (size_t)KVDIM * KDIM;   // 4194304
    size_t t = ((size_t)blockIdx.x * blockDim.x + threadIdx.x) * 4;
    const float* src; __half* dst; size_t off;
    if (t < NB)                { src = x;  dst = g_xh;  off = t; }
    else if (t < 2 * NB)       { src = wq; dst = g_wqh; off = t - NB; }
    else if (t < 2 * NB + NK)  { src = wk; dst = g_wkh; off = t - 2 * NB; }
    else if (t < 2 * NB + 2 * NK) { src = wv; dst = g_wvh; off = t - 2 * NB - NK; }
    else if (t < 3 * NB + 2 * NK) { src = wo; dst = g_woh; off = t - 2 * NB - 2 * NK; }
    else return;
    float4 f = *(const float4*)(src + off);
    __half2 a = __floats2half2_rn(f.x, f.y);
    __half2 b = __floats2half2_rn(f.z, f.w);
    *(uint2*)(dst + off) = make_uint2(*(uint32_t*)&a, *(uint32_t*)&b);
}

// ---------------------------------------------------------------------------
// GEMM: C[M,N] = Ah[M,K] * Bh[N,K]^T, single fp16 MMA, fp32 accum.
// 128x256 block tile, 8 warps (2x4), 64x64 warp tile, BK=64, double-buffered.
// MODE 0: fp32 output. MODE 1: fp16 output. MODE 2: RoPE (interleaved pairs)
// applied to fp32 accumulators, then fp16 output.
// ---------------------------------------------------------------------------
#define BM 128
#define BN 256
#define BK 64
#define PADC 72
#define A_BYTES (BM * PADC * 2)            // 18432
#define B_BYTES (BN * PADC * 2)            // 36864
#define STAGE_BYTES (A_BYTES + B_BYTES)    // 55296
#define GEMM_SMEM   (2 * STAGE_BYTES)      // 110592

template<int MODE>
__global__ void __launch_bounds__(256)
gemm_fp16x1(const __half* __restrict__ Ah,
            const __half* __restrict__ Bh,
            void* __restrict__ Cv, int N,
            const float* __restrict__ cosp,
            const float* __restrict__ sinp)
{
    extern __shared__ char smem[];
    const int K = KDIM;
    const uint32_t sbase = smem_u32(smem);
    const int tid = threadIdx.x;
    const int wid = tid >> 5;
    const int lane = tid & 31;
    const int warp_m = wid >> 2;
    const int warp_n = wid & 3;
    const int bm = blockIdx.y * BM;
    const int bn = blockIdx.x * BN;
    const int NCH = K / BK;

    float acc[4][8][4];
#pragma unroll
    for (int i = 0; i < 4; i++)
#pragma unroll
        for (int j = 0; j < 8; j++)
#pragma unroll
            for (int r = 0; r < 4; r++) acc[i][j][r] = 0.f;

    const int a_row = lane & 15;
    const int a_col = (lane >> 4) * 8;
    const int b_row = ((lane >> 4) * 8) + (lane & 7);
    const int b_col = ((lane >> 3) & 1) * 8;

    auto load_stage = [&](int ch, int st) {
        if (ch < NCH) {
            const int kc = ch * BK;
            const uint32_t base = sbase + st * STAGE_BYTES;
#pragma unroll
            for (int i = 0; i < 12; i++) {
                int u = tid + i * 256;
                uint32_t dst; const __half* src;
                if (u < 1024) {
                    int row = u >> 3, ck = (u & 7) * 8;
                    src = Ah + (size_t)(bm + row) * K + kc + ck;
                    dst = base + (uint32_t)(row * PADC + ck) * 2;
                } else {
                    int idx = u - 1024;
                    int row = idx >> 3, ck = (idx & 7) * 8;
                    src = Bh + (size_t)(bn + row) * K + kc + ck;
                    dst = base + A_BYTES + (uint32_t)(row * PADC + ck) * 2;
                }
                CP_ASYNC16(dst, src);
            }
        }
        CP_COMMIT();
    };

    load_stage(0, 0);
    load_stage(1, 1);

    for (int ch = 0; ch < NCH; ch++) {
        const int st = ch & 1;
        CP_WAIT1();
        __syncthreads();
        const uint32_t tb = sbase + st * STAGE_BYTES;
#pragma unroll
        for (int ks = 0; ks < 4; ks++) {
            uint32_t afr[4][4];
#pragma unroll
            for (int mt = 0; mt < 4; mt++) {
                uint32_t addr = tb
                    + (uint32_t)((warp_m * 64 + mt * 16 + a_row) * PADC
                                 + ks * 16 + a_col) * 2;
                ldsm4(afr[mt], addr);
            }
#pragma unroll
            for (int np = 0; np < 4; np++) {
                uint32_t bfr[4];
                uint32_t addr = tb + A_BYTES
                    + (uint32_t)((warp_n * 64 + np * 16 + b_row) * PADC
                                 + ks * 16 + b_col) * 2;
                ldsm4(bfr, addr);
#pragma unroll
                for (int h2 = 0; h2 < 2; h2++) {
                    int nt = np * 2 + h2;
#pragma unroll
                    for (int mt = 0; mt < 4; mt++)
                        mma16816h(acc[mt][nt], afr[mt],
                                  bfr[h2 * 2], bfr[h2 * 2 + 1]);
                }
            }
        }
        __syncthreads();
        load_stage(ch + 2, st);
    }

    // ---- epilogue -----------------------------------------------------------
#pragma unroll
    for (int mt = 0; mt < 4; mt++)
#pragma unroll
        for (int nt = 0; nt < 8; nt++) {
            int row0 = bm + warp_m * 64 + mt * 16 + (lane >> 2);
            int col  = bn + warp_n * 64 + nt * 8 + (lane & 3) * 2;
            float v0 = acc[mt][nt][0], v1 = acc[mt][nt][1];
            float v2 = acc[mt][nt][2], v3 = acc[mt][nt][3];
            if (MODE == 0) {
                float* C = (float*)Cv;
                *(float2*)(C + (size_t)row0 * N + col) = make_float2(v0, v1);
                *(float2*)(C + (size_t)(row0 + 8) * N + col) = make_float2(v2, v3);
            } else {
                if (MODE == 2) {
                    int i  = (col & 127) >> 1;
                    int s0 = row0 & (S_LEN - 1);
                    int s1 = (row0 + 8) & (S_LEN - 1);
                    float c0 = cosp[s0 * 64 + i], n0 = sinp[s0 * 64 + i];
                    float c1 = cosp[s1 * 64 + i], n1 = sinp[s1 * 64 + i];
                    float t0 = v0 * c0 - v1 * n0; v1 = v0 * n0 + v1 * c0; v0 = t0;
                    float t2 = v2 * c1 - v3 * n1; v3 = v2 * n1 + v3 * c1; v2 = t2;
                }
                __half* C = (__half*)Cv;
                *(__half2*)(C + (size_t)row0 * N + col) = __floats2half2_rn(v0, v1);
                *(__half2*)(C + (size_t)(row0 + 8) * N + col) = __floats2half2_rn(v2, v3);
            }
        }
}

// ---------------------------------------------------------------------------
// Tensor-core causal flash attention, single fp16 MMA per tile (unchanged).
// ---------------------------------------------------------------------------
#define APAD   136
#define QSP    (128 * APAD * 2)
#define KVSP   (64 * APAD * 2)
#define ASTAGE (2 * KVSP)
#define ATTN_SMEM (QSP + 2 * ASTAGE)

__global__ void __launch_bounds__(256)
attn_mma()
{
    extern __shared__ char smem[];
    const uint32_t sbase = smem_u32(smem);
    const int tid = threadIdx.x;
    const int warp = tid >> 5;
    const int lane = tid & 31;
    const int qb = blockIdx.x;
    const int h  = blockIdx.y;
    const int b  = blockIdx.z;
    const int kvh = h >> 2;
    const int q0 = qb * 128;
    const int bs = b * S_LEN;
    const int ntiles = 2 * qb + 2;

    const __half* k_b = g_k16 + (size_t)bs * KVDIM + kvh * HD;
    const __half* v_b = g_v16 + (size_t)bs * KVDIM + kvh * HD;

    {
        const __half* q_b = g_q16 + (size_t)(bs + q0) * DIM + h * HD;
#pragma unroll
        for (int i = 0; i < 8; i++) {
            int u = tid + i * 256;
            int row = u >> 4, ck = u & 15;
            const __half* src = q_b + (size_t)row * DIM + ck * 8;
            uint32_t dst = sbase + (uint32_t)(row * APAD + ck * 8) * 2;
            CP_ASYNC16(dst, src);
        }
    }

    auto load_kv = [&](int t, int st) {
        if (t < ntiles) {
            const int k0 = t * 64;
            const uint32_t base = sbase + QSP + st * ASTAGE;
#pragma unroll
            for (int i = 0; i < 8; i++) {
                int u = tid + i * 256;
                int isV = u >> 10;
                int idx = u & 1023;
                int row = idx >> 4, ck = idx & 15;
                const __half* src = (isV ? v_b : k_b)
                                  + (size_t)(k0 + row) * KVDIM + ck * 8;
                uint32_t dst = base + isV * KVSP
                             + (uint32_t)(row * APAD + ck * 8) * 2;
                CP_ASYNC16(dst, src);
            }
        }
        CP_COMMIT();
    };

    load_kv(0, 0);
    load_kv(1, 1);

    const int r0 = lane >> 2;
    const int grow0 = q0 + warp * 16 + r0;
    const int grow1 = grow0 + 8;
    const int wmaxrow = q0 + warp * 16 + 15;
    const float scale = 0.08838834764831845f;

    float m0 = -1e30f, m1 = -1e30f, l0 = 0.f, l1 = 0.f;
    float oacc[16][4];
#pragma unroll
    for (int i = 0; i < 16; i++)
#pragma unroll
        for (int j = 0; j < 4; j++) oacc[i][j] = 0.f;

    const int qa_off = (warp * 16 + (lane & 15)) * APAD + (lane >> 4) * 8;
    const int kb_row = ((lane >> 4) * 8) + (lane & 7);
    const int kb_colh = ((lane >> 3) & 1) * 8;
    const int v_key = (lane & 7) + ((lane >> 3) & 1) * 8;
    const int v_hd  = (lane >> 4) * 8;

    for (int t = 0; t < ntiles; t++) {
        CP_WAIT1();
        __syncthreads();
        const int k0 = t * 64;
        const uint32_t kb = sbase + QSP + (t & 1) * ASTAGE;

        if (k0 <= wmaxrow) {
            float sacc[8][4];
#pragma unroll
            for (int i = 0; i < 8; i++)
#pragma unroll
                for (int j = 0; j < 4; j++) sacc[i][j] = 0.f;

#pragma unroll
            for (int ks = 0; ks < 8; ks++) {
                uint32_t qfr[4];
                ldsm4(qfr, sbase + (uint32_t)(qa_off + ks * 16) * 2);
#pragma unroll
                for (int np = 0; np < 4; np++) {
                    uint32_t kfr[4];
                    uint32_t kaddr = kb
                        + (uint32_t)((np * 16 + kb_row) * APAD + ks * 16 + kb_colh) * 2;
                    ldsm4(kfr, kaddr);
                    mma16816h(sacc[np * 2],     qfr, kfr[0], kfr[1]);
                    mma16816h(sacc[np * 2 + 1], qfr, kfr[2], kfr[3]);
                }
            }

            const bool domask = (t >= 2 * qb);
            float mx0 = -1e30f, mx1 = -1e30f;
#pragma unroll
            for (int nt = 0; nt < 8; nt++) {
                float s0 = sacc[nt][0] * scale;
                float s1 = sacc[nt][1] * scale;
                float s2 = sacc[nt][2] * scale;
                float s3 = sacc[nt][3] * scale;
                if (domask) {
                    int gc = k0 + nt * 8 + 2 * (lane & 3);
                    if (gc > grow0)     s0 = -1e30f;
                    if (gc + 1 > grow0) s1 = -1e30f;
                    if (gc > grow1)     s2 = -1e30f;
                    if (gc + 1 > grow1) s3 = -1e30f;
                }
                sacc[nt][0] = s0; sacc[nt][1] = s1;
                sacc[nt][2] = s2; sacc[nt][3] = s3;
                mx0 = fmaxf(mx0, fmaxf(s0, s1));
                mx1 = fmaxf(mx1, fmaxf(s2, s3));
            }
            mx0 = fmaxf(mx0, __shfl_xor_sync(0xffffffffu, mx0, 1));
            mx0 = fmaxf(mx0, __shfl_xor_sync(0xffffffffu, mx0, 2));
            mx1 = fmaxf(mx1, __shfl_xor_sync(0xffffffffu, mx1, 1));
            mx1 = fmaxf(mx1, __shfl_xor_sync(0xffffffffu, mx1, 2));
            float mn0 = fmaxf(m0, mx0), mn1 = fmaxf(m1, mx1);
            float c0 = __expf(m0 - mn0), c1 = __expf(m1 - mn1);
            m0 = mn0; m1 = mn1;
            l0 *= c0; l1 *= c1;
#pragma unroll
            for (int nt = 0; nt < 16; nt++) {
                oacc[nt][0] *= c0; oacc[nt][1] *= c0;
                oacc[nt][2] *= c1; oacc[nt][3] *= c1;
            }
#pragma unroll
            for (int nt = 0; nt < 8; nt++) {
                float p0 = __expf(sacc[nt][0] - m0);
                float p1 = __expf(sacc[nt][1] - m0);
                float p2 = __expf(sacc[nt][2] - m1);
                float p3 = __expf(sacc[nt][3] - m1);
                sacc[nt][0] = p0; sacc[nt][1] = p1;
                sacc[nt][2] = p2; sacc[nt][3] = p3;
                l0 += p0 + p1; l1 += p2 + p3;
            }

#pragma unroll
            for (int kc = 0; kc < 4; kc++) {
                uint32_t ph[4];
#pragma unroll
                for (int half = 0; half < 2; half++) {
                    const float* pp = sacc[2 * kc + half];
                    __half2 h01 = __floats2half2_rn(pp[0], pp[1]);
                    __half2 h23 = __floats2half2_rn(pp[2], pp[3]);
                    ph[half * 2 + 0] = *(uint32_t*)&h01;
                    ph[half * 2 + 1] = *(uint32_t*)&h23;
                }
#pragma unroll
                for (int np = 0; np < 8; np++) {
                    uint32_t vfr[4];
                    uint32_t vaddr = kb + KVSP
                        + (uint32_t)((kc * 16 + v_key) * APAD + np * 16 + v_hd) * 2;
                    ldsm4t(vfr, vaddr);
                    mma16816h(oacc[2 * np],     ph, vfr[0], vfr[1]);
                    mma16816h(oacc[2 * np + 1], ph, vfr[2], vfr[3]);
                }
            }
        }
        __syncthreads();
        load_kv(t + 2, t & 1);
    }

    l0 += __shfl_xor_sync(0xffffffffu, l0, 1);
    l0 += __shfl_xor_sync(0xffffffffu, l0, 2);
    l1 += __shfl_xor_sync(0xffffffffu, l1, 1);
    l1 += __shfl_xor_sync(0xffffffffu, l1, 2);
    float inv0 = 1.f / l0, inv1 = 1.f / l1;

    size_t gr0 = (size_t)(bs + grow0);
    size_t gr1 = (size_t)(bs + grow1);
#pragma unroll
    for (int nt = 0; nt < 16; nt++) {
        int col = h * HD + nt * 8 + 2 * (lane & 3);
        __half2 h0 = __floats2half2_rn(oacc[nt][0] * inv0, oacc[nt][1] * inv0);
        __half2 h1 = __floats2half2_rn(oacc[nt][2] * inv1, oacc[nt][3] * inv1);
        *(__half2*)(g_ah + gr0 * DIM + col) = h0;
        *(__half2*)(g_ah + gr1 * DIM + col) = h1;
    }
}

// ---------------------------------------------------------------------------
extern "C" void kernel_launch(void* const* d_in, const int* in_sizes, int n_in,
                              void* d_out, int out_size)
{
    (void)in_sizes; (void)n_in; (void)out_size;
    const float* x  = (const float*)d_in[0];
    const float* wq = (const float*)d_in[1];
    const float* wk = (const float*)d_in[2];
    const float* wv = (const float*)d_in[3];
    const float* wo = (const float*)d_in[4];
    const float* fc = (const float*)d_in[5];
    const float* fs = (const float*)d_in[6];
    float* out = (float*)d_out;

    __half *xh, *wqh, *wkh, *wvh, *woh, *ah, *q16, *k16, *v16;
    cudaGetSymbolAddress((void**)&xh,  g_xh);
    cudaGetSymbolAddress((void**)&wqh, g_wqh);
    cudaGetSymbolAddress((void**)&wkh, g_wkh);
    cudaGetSymbolAddress((void**)&wvh, g_wvh);
    cudaGetSymbolAddress((void**)&woh, g_woh);
    cudaGetSymbolAddress((void**)&ah,  g_ah);
    cudaGetSymbolAddress((void**)&q16, g_q16);
    cudaGetSymbolAddress((void**)&k16, g_k16);
    cudaGetSymbolAddress((void**)&v16, g_v16);

    cudaFuncSetAttribute(gemm_fp16x1<0>,
                         cudaFuncAttributeMaxDynamicSharedMemorySize, GEMM_SMEM);
    cudaFuncSetAttribute(gemm_fp16x1<1>,
                         cudaFuncAttributeMaxDynamicSharedMemorySize, GEMM_SMEM);
    cudaFuncSetAttribute(gemm_fp16x1<2>,
                         cudaFuncAttributeMaxDynamicSharedMemorySize, GEMM_SMEM);
    cudaFuncSetAttribute(attn_mma,
                         cudaFuncAttributeMaxDynamicSharedMemorySize, ATTN_SMEM);

    // Fused fp32 -> fp16 rounding of x + all four weights (one launch)
    const size_t total_elems = 3 * (size_t)MROWS * KDIM + 2 * (size_t)KVDIM * KDIM;
    const int rblocks = (int)((total_elems / 4 + 255) / 256);
    round_all_kernel<<<rblocks, 256>>>(x, wq, wk, wv, wo);

    // Q/K projections with fused RoPE -> fp16 ; V projection -> fp16
    gemm_fp16x1<2><<<dim3(DIM / BN,   MROWS / BM), 256, GEMM_SMEM>>>(
        xh, wqh, q16, DIM, fc, fs);
    gemm_fp16x1<2><<<dim3(KVDIM / BN, MROWS / BM), 256, GEMM_SMEM>>>(
        xh, wkh, k16, KVDIM, fc, fs);
    gemm_fp16x1<1><<<dim3(KVDIM / BN, MROWS / BM), 256, GEMM_SMEM>>>(
        xh, wvh, v16, KVDIM, nullptr, nullptr);

    // Tensor-core flash attention (fp16) -> writes g_ah
    attn_mma<<<dim3(S_LEN / 128, NH, BATCH), 256, ATTN_SMEM>>>();

    // O projection -> fp32 output
    gemm_fp16x1<0><<<dim3(DIM / BN, MROWS / BM), 256, GEMM_SMEM>>>(
        ah, woh, out, DIM, nullptr, nullptr);
}